// round 1
// baseline (speedup 1.0000x reference)
#include <cuda_runtime.h>
#include <math.h>

// Problem constants
#define EDIM 384
#define GDIM 256
#define HNUM 6
#define DHH  64
#define OUTD 256
#define MAXN 1024
#define HE   (HNUM*EDIM)   // 2304

// ---------------- device scratch (no allocations allowed) ----------------
__device__ __align__(16) float g_q[EDIM];            // projected+scaled query
__device__ __align__(16) float g_wk[HNUM*EDIM];      // effective score weights per head
__device__ __align__(16) float g_Wc[OUTD*EDIM];      // Wp @ Wo
__device__ __align__(16) float g_Wfinal[OUTD*HE];    // fused output weights [o][h*384+e]
__device__ __align__(16) float g_bfinal[OUTD];
__device__            int   g_off[GDIM];             // segment offsets
__device__ __align__(16) float g_accx[GDIM*HE];      // attn-weighted x sums [g][h*384+e]

// ---------------- helpers ----------------
__device__ __forceinline__ float warp_sum(float v) {
#pragma unroll
    for (int s = 16; s > 0; s >>= 1) v += __shfl_xor_sync(0xffffffffu, v, s);
    return v;
}
__device__ __forceinline__ float warp_max(float v) {
#pragma unroll
    for (int s = 16; s > 0; s >>= 1) v = fmaxf(v, __shfl_xor_sync(0xffffffffu, v, s));
    return v;
}

// ---------------- K0: q = (Wq @ query + bq) / sqrt(DH) ----------------
// warp per output row
__global__ void qproj_kernel(const float* __restrict__ Wq,
                             const float* __restrict__ query,
                             const float* __restrict__ bq) {
    int gw = (blockIdx.x * blockDim.x + threadIdx.x) >> 5;
    int lane = threadIdx.x & 31;
    if (gw >= EDIM) return;
    float s = 0.f;
    for (int j = lane; j < EDIM; j += 32) s += Wq[(size_t)gw * EDIM + j] * query[j];
    s = warp_sum(s);
    if (lane == 0) g_q[gw] = (s + bq[gw]) * 0.125f;   // 1/sqrt(64)
}

// ---------------- K1: w_h[e] = sum_d q[h*64+d] * Wk[h*64+d, e] ----------------
// grid = H blocks, block = EDIM threads
__global__ void wkeff_kernel(const float* __restrict__ Wk) {
    int h = blockIdx.x;
    int e = threadIdx.x;
    __shared__ float qs[DHH];
    if (e < DHH) qs[e] = g_q[h * DHH + e];
    __syncthreads();
    float s = 0.f;
#pragma unroll 8
    for (int d = 0; d < DHH; d++)
        s += qs[d] * Wk[(size_t)(h * DHH + d) * EDIM + e];
    g_wk[h * EDIM + e] = s;
}

// ---------------- K2: exclusive prefix sum of sizes ----------------
__global__ void scan_kernel(const int* __restrict__ sizes) {
    __shared__ int s[GDIM];
    int t = threadIdx.x;
    int v = sizes[t];
    s[t] = v;
    __syncthreads();
    for (int d = 1; d < GDIM; d <<= 1) {
        int add = (t >= d) ? s[t - d] : 0;
        __syncthreads();
        s[t] += add;
        __syncthreads();
    }
    g_off[t] = s[t] - v;
}

// ---------------- generic 32x32-tiled fp32 GEMM ----------------
// C[M,N] = A[M,K] @ B (+ bias[n]).  B is [K,N] (TB=false) or [N,K] (TB=true).
template <bool TB, bool BIAS>
__global__ void gemm32(const float* __restrict__ A, int lda,
                       const float* __restrict__ B, int ldb,
                       float* __restrict__ C, int ldc,
                       const float* __restrict__ bias,
                       int M, int N, int K) {
    __shared__ float As[32][33];
    __shared__ float Bs[32][33];   // Bs[k][n]
    int tid = threadIdx.y * 16 + threadIdx.x;
    int bm = blockIdx.y * 32, bn = blockIdx.x * 32;
    float a00 = 0.f, a01 = 0.f, a10 = 0.f, a11 = 0.f;

    for (int k0 = 0; k0 < K; k0 += 32) {
        for (int i = tid; i < 1024; i += 256) {
            int r = i >> 5, c = i & 31;
            int m = bm + r, k = k0 + c;
            As[r][c] = (m < M && k < K) ? A[(size_t)m * lda + k] : 0.f;
        }
        if (TB) {
            for (int i = tid; i < 1024; i += 256) {
                int r = i >> 5, c = i & 31;      // r = n-idx, c = k-idx (contig)
                int nn = bn + r, k = k0 + c;
                Bs[c][r] = (nn < N && k < K) ? B[(size_t)nn * ldb + k] : 0.f;
            }
        } else {
            for (int i = tid; i < 1024; i += 256) {
                int r = i >> 5, c = i & 31;      // r = k-idx, c = n-idx (contig)
                int k = k0 + r, nn = bn + c;
                Bs[r][c] = (k < K && nn < N) ? B[(size_t)k * ldb + nn] : 0.f;
            }
        }
        __syncthreads();
#pragma unroll
        for (int kk = 0; kk < 32; kk++) {
            float x0 = As[threadIdx.y * 2 + 0][kk];
            float x1 = As[threadIdx.y * 2 + 1][kk];
            float y0 = Bs[kk][threadIdx.x * 2 + 0];
            float y1 = Bs[kk][threadIdx.x * 2 + 1];
            a00 = fmaf(x0, y0, a00);
            a01 = fmaf(x0, y1, a01);
            a10 = fmaf(x1, y0, a10);
            a11 = fmaf(x1, y1, a11);
        }
        __syncthreads();
    }
    int m0 = bm + threadIdx.y * 2, n0 = bn + threadIdx.x * 2;
    float b0 = 0.f, b1 = 0.f;
    if (BIAS) {
        if (n0 < N) b0 = bias[n0];
        if (n0 + 1 < N) b1 = bias[n0 + 1];
    }
    if (m0 < M) {
        if (n0 < N)     C[(size_t)m0 * ldc + n0]     = a00 + b0;
        if (n0 + 1 < N) C[(size_t)m0 * ldc + n0 + 1] = a01 + b1;
    }
    if (m0 + 1 < M) {
        if (n0 < N)     C[(size_t)(m0 + 1) * ldc + n0]     = a10 + b0;
        if (n0 + 1 < N) C[(size_t)(m0 + 1) * ldc + n0 + 1] = a11 + b1;
    }
}

// ---------------- K4: bfinal[o] = Wc[o,:].bv + Wp[o,:].bo + bp[o] ----------------
__global__ void bfinal_kernel(const float* __restrict__ Wp,
                              const float* __restrict__ bo,
                              const float* __restrict__ bp,
                              const float* __restrict__ bv) {
    int gw = (blockIdx.x * blockDim.x + threadIdx.x) >> 5;
    int lane = threadIdx.x & 31;
    if (gw >= OUTD) return;
    float s = 0.f;
    for (int j = lane; j < EDIM; j += 32)
        s += g_Wc[(size_t)gw * EDIM + j] * bv[j] + Wp[(size_t)gw * EDIM + j] * bo[j];
    s = warp_sum(s);
    if (lane == 0) g_bfinal[gw] = s + bp[gw];
}

// ---------------- K5: main attention kernel ----------------
// grid = G blocks, block = 384 threads (12 warps).
__global__ void __launch_bounds__(384, 1)
attn_kernel(const float* __restrict__ x, const int* __restrict__ sizes) {
    __shared__ float s_sc[HNUM][MAXN];   // 24 KB scores / unnormalized attn
    __shared__ float s_inv[HNUM];

    int g = blockIdx.x;
    int off = g_off[g];
    int size = sizes[g];
    int tid = threadIdx.x;
    int warp = tid >> 5;
    int lane = tid & 31;

    // per-lane effective weights: col = j*128 + lane*4 + c, j<3, c<4
    float4 w[HNUM][3];
#pragma unroll
    for (int h = 0; h < HNUM; h++)
#pragma unroll
        for (int j = 0; j < 3; j++)
            w[h][j] = *(const float4*)(&g_wk[h * EDIM + j * 128 + lane * 4]);

    // ---- phase 1: scores (warp per node) ----
    for (int n = warp; n < size; n += 12) {
        const float* row = x + (size_t)(off + n) * EDIM;
        float4 x0 = *(const float4*)(row + lane * 4);
        float4 x1 = *(const float4*)(row + 128 + lane * 4);
        float4 x2 = *(const float4*)(row + 256 + lane * 4);
        float p[HNUM];
#pragma unroll
        for (int h = 0; h < HNUM; h++) {
            float s = w[h][0].x * x0.x + w[h][0].y * x0.y + w[h][0].z * x0.z + w[h][0].w * x0.w;
            s = fmaf(w[h][1].x, x1.x, s); s = fmaf(w[h][1].y, x1.y, s);
            s = fmaf(w[h][1].z, x1.z, s); s = fmaf(w[h][1].w, x1.w, s);
            s = fmaf(w[h][2].x, x2.x, s); s = fmaf(w[h][2].y, x2.y, s);
            s = fmaf(w[h][2].z, x2.z, s); s = fmaf(w[h][2].w, x2.w, s);
            p[h] = s;
        }
#pragma unroll
        for (int sft = 16; sft > 0; sft >>= 1) {
#pragma unroll
            for (int h = 0; h < HNUM; h++)
                p[h] += __shfl_xor_sync(0xffffffffu, p[h], sft);
        }
        if (lane == 0) {
#pragma unroll
            for (int h = 0; h < HNUM; h++) s_sc[h][n] = p[h];
        }
    }
    __syncthreads();

    // ---- phase 2: per-head softmax (warp h handles head h) ----
    if (warp < HNUM) {
        int h = warp;
        float m = -1e30f;
        for (int n = lane; n < size; n += 32) m = fmaxf(m, s_sc[h][n]);
        m = warp_max(m);
        float sum = 0.f;
        for (int n = lane; n < size; n += 32) {
            float e = __expf(s_sc[h][n] - m);
            s_sc[h][n] = e;
            sum += e;
        }
        sum = warp_sum(sum);
        if (lane == 0) s_inv[h] = 1.f / sum;
    }
    __syncthreads();

    // ---- phase 3: weighted sums (thread per column e) ----
    int e = tid;  // 0..383
    const float* px = x + (size_t)off * EDIM + e;
    float acc[HNUM];
#pragma unroll
    for (int h = 0; h < HNUM; h++) acc[h] = 0.f;

    int n = 0;
    for (; n + 4 <= size; n += 4) {
        float xv0 = px[(size_t)(n + 0) * EDIM];
        float xv1 = px[(size_t)(n + 1) * EDIM];
        float xv2 = px[(size_t)(n + 2) * EDIM];
        float xv3 = px[(size_t)(n + 3) * EDIM];
#pragma unroll
        for (int h = 0; h < HNUM; h++) {
            float a = acc[h];
            a = fmaf(s_sc[h][n + 0], xv0, a);
            a = fmaf(s_sc[h][n + 1], xv1, a);
            a = fmaf(s_sc[h][n + 2], xv2, a);
            a = fmaf(s_sc[h][n + 3], xv3, a);
            acc[h] = a;
        }
    }
    for (; n < size; n++) {
        float xv = px[(size_t)n * EDIM];
#pragma unroll
        for (int h = 0; h < HNUM; h++) acc[h] = fmaf(s_sc[h][n], xv, acc[h]);
    }
#pragma unroll
    for (int h = 0; h < HNUM; h++)
        g_accx[(size_t)g * HE + h * EDIM + e] = acc[h] * s_inv[h];
}

// ---------------- launch ----------------
extern "C" void kernel_launch(void* const* d_in, const int* in_sizes, int n_in,
                              void* d_out, int out_size) {
    const float* node_feat = (const float*)d_in[0];
    const int*   sizes     = (const int*)d_in[1];
    const float* query     = (const float*)d_in[2];
    const float* Wq        = (const float*)d_in[3];
    const float* bq        = (const float*)d_in[4];
    const float* Wk        = (const float*)d_in[5];
    /* bk = d_in[6] — cancels in softmax */
    const float* Wv        = (const float*)d_in[7];
    const float* bv        = (const float*)d_in[8];
    const float* Wo        = (const float*)d_in[9];
    const float* bo        = (const float*)d_in[10];
    const float* Wp        = (const float*)d_in[11];
    const float* bp        = (const float*)d_in[12];
    float* out = (float*)d_out;

    // resolve device-scratch addresses for GEMM args
    float *pWc, *pWfinal, *pbfinal, *paccx;
    cudaGetSymbolAddress((void**)&pWc, g_Wc);
    cudaGetSymbolAddress((void**)&pWfinal, g_Wfinal);
    cudaGetSymbolAddress((void**)&pbfinal, g_bfinal);
    cudaGetSymbolAddress((void**)&paccx, g_accx);

    dim3 tb16(16, 16);

    // precompute (independent of node data)
    qproj_kernel<<<96, 128>>>(Wq, query, bq);
    wkeff_kernel<<<HNUM, EDIM>>>(Wk);
    scan_kernel<<<1, GDIM>>>(sizes);

    // Wc = Wp @ Wo   [256,384] = [256,384] @ [384,384]
    gemm32<false, false><<<dim3(EDIM / 32, OUTD / 32), tb16>>>(
        Wp, EDIM, Wo, EDIM, pWc, EDIM, nullptr, OUTD, EDIM, EDIM);

    // Wfinal[o, h*384+e] = Wc[o, h*64:..] @ Wv[h*64:.., :]   (6 small GEMMs)
    for (int h = 0; h < HNUM; h++) {
        gemm32<false, false><<<dim3(EDIM / 32, OUTD / 32), tb16>>>(
            pWc + h * DHH, EDIM,
            Wv + (size_t)h * DHH * EDIM, EDIM,
            pWfinal + h * EDIM, HE,
            nullptr, OUTD, EDIM, DHH);
    }
    bfinal_kernel<<<64, 128>>>(Wp, bo, bp, bv);

    // main attention: accx[g, h, e]
    attn_kernel<<<GDIM, EDIM>>>(node_feat, sizes);

    // res[g, o] = accx[g, :] . Wfinal[o, :] + bfinal[o]
    gemm32<true, true><<<dim3(OUTD / 32, GDIM / 32), tb16>>>(
        paccx, HE, pWfinal, HE, out, OUTD, pbfinal, GDIM, OUTD, HE);
}

// round 2
// speedup vs baseline: 1.7719x; 1.7719x over previous
#include <cuda_runtime.h>
#include <math.h>

// Problem constants
#define EDIM 384
#define GDIM 256
#define HNUM 6
#define DHH  64
#define OUTD 256
#define MAXN 1024
#define NMAX 131072
#define HE   (HNUM*EDIM)   // 2304

// ---------------- device scratch ----------------
__device__ __align__(16) float g_q[EDIM];
__device__ __align__(16) float g_wk[HNUM*EDIM];
__device__ __align__(16) float g_Wc[OUTD*EDIM];      // Wp @ Wo
__device__ __align__(16) float g_cb[OUTD];           // Wp.bo + bp
__device__            int   g_off[GDIM + 1];
__device__ __align__(16) float g_scores[HNUM*NMAX];  // scores -> attn (in place)
__device__ __align__(16) float g_accx[GDIM*HE];      // attn-weighted x sums
__device__ __align__(16) float g_pooled[GDIM*EDIM];  // pooled incl. bv

// ---------------- helpers ----------------
__device__ __forceinline__ float warp_sum(float v) {
#pragma unroll
    for (int s = 16; s > 0; s >>= 1) v += __shfl_xor_sync(0xffffffffu, v, s);
    return v;
}
__device__ __forceinline__ float warp_max(float v) {
#pragma unroll
    for (int s = 16; s > 0; s >>= 1) v = fmaxf(v, __shfl_xor_sync(0xffffffffu, v, s));
    return v;
}

// ---------------- K0: q = (Wq @ query + bq) / sqrt(DH) ----------------
__global__ void qproj_kernel(const float* __restrict__ Wq,
                             const float* __restrict__ query,
                             const float* __restrict__ bq) {
    int gw = (blockIdx.x * blockDim.x + threadIdx.x) >> 5;
    int lane = threadIdx.x & 31;
    if (gw >= EDIM) return;
    float s = 0.f;
    for (int j = lane; j < EDIM; j += 32) s += Wq[(size_t)gw * EDIM + j] * query[j];
    s = warp_sum(s);
    if (lane == 0) g_q[gw] = (s + bq[gw]) * 0.125f;
}

// ---------------- K1: w_h[e] = sum_d q[h*64+d] * Wk[h*64+d, e] ----------------
__global__ void wkeff_kernel(const float* __restrict__ Wk) {
    int h = blockIdx.x;
    int e = threadIdx.x;
    __shared__ float qs[DHH];
    if (e < DHH) qs[e] = g_q[h * DHH + e];
    __syncthreads();
    float s = 0.f;
#pragma unroll 8
    for (int d = 0; d < DHH; d++)
        s += qs[d] * Wk[(size_t)(h * DHH + d) * EDIM + e];
    g_wk[h * EDIM + e] = s;
}

// ---------------- K2: exclusive prefix scan of sizes (+ total) ----------------
__global__ void scan_kernel(const int* __restrict__ sizes) {
    __shared__ int s[GDIM];
    int t = threadIdx.x;
    int v = sizes[t];
    s[t] = v;
    __syncthreads();
    for (int d = 1; d < GDIM; d <<= 1) {
        int add = (t >= d) ? s[t - d] : 0;
        __syncthreads();
        s[t] += add;
        __syncthreads();
    }
    g_off[t] = s[t] - v;
    if (t == GDIM - 1) g_off[GDIM] = s[t];
}

// ---------------- K3: cb[o] = Wp[o,:].bo + bp[o] ----------------
__global__ void cb_kernel(const float* __restrict__ Wp,
                          const float* __restrict__ bo,
                          const float* __restrict__ bp) {
    int gw = (blockIdx.x * blockDim.x + threadIdx.x) >> 5;
    int lane = threadIdx.x & 31;
    if (gw >= OUTD) return;
    float s = 0.f;
    for (int j = lane; j < EDIM; j += 32) s += Wp[(size_t)gw * EDIM + j] * bo[j];
    s = warp_sum(s);
    if (lane == 0) g_cb[gw] = s + bp[gw];
}

// ---------------- 64x64-tiled fp32 GEMM, 4x4 microtile ----------------
// C[M,N] = A[M,K] @ B (+ bias[n]).  B is [K,N] (TB=false) or [N,K] (TB=true).
// Batched over blockIdx.z via zA/zB/zC/zBias pointer strides.
template <bool TB, bool BIAS>
__global__ void __launch_bounds__(256)
gemm64(const float* __restrict__ A, int lda,
       const float* __restrict__ B, int ldb,
       float* __restrict__ C, int ldc,
       const float* __restrict__ bias,
       int M, int N, int K,
       int zA, int zB, int zC, int zBias) {
    A += (size_t)blockIdx.z * zA;
    B += (size_t)blockIdx.z * zB;
    C += (size_t)blockIdx.z * zC;
    if (BIAS) bias += (size_t)blockIdx.z * zBias;

    __shared__ float As[32][65];   // [k][m]
    __shared__ float Bs[32][65];   // [k][n]
    int tid = threadIdx.x;
    int bm = blockIdx.y * 64, bn = blockIdx.x * 64;
    int tx = tid & 15, ty = tid >> 4;

    float acc[4][4];
#pragma unroll
    for (int i = 0; i < 4; i++)
#pragma unroll
        for (int j = 0; j < 4; j++) acc[i][j] = 0.f;

    for (int k0 = 0; k0 < K; k0 += 32) {
        {   // A tile: As[k][m]
            int kk = tid & 31, m0 = tid >> 5;   // m0 0..7
#pragma unroll
            for (int i = 0; i < 8; i++) {
                int mm = m0 + i * 8;
                int gm = bm + mm, gk = k0 + kk;
                As[kk][mm] = (gm < M) ? A[(size_t)gm * lda + gk] : 0.f;
            }
        }
        if (TB) {
            int kk = tid & 31, n0 = tid >> 5;
#pragma unroll
            for (int i = 0; i < 8; i++) {
                int nn = n0 + i * 8;
                int gn = bn + nn, gk = k0 + kk;
                Bs[kk][nn] = (gn < N) ? B[(size_t)gn * ldb + gk] : 0.f;
            }
        } else {
            int nn = tid & 63, kq = tid >> 6;   // kq 0..3
#pragma unroll
            for (int i = 0; i < 8; i++) {
                int k2 = kq + i * 4;
                int gn = bn + nn, gk = k0 + k2;
                Bs[k2][nn] = (gn < N) ? B[(size_t)gk * ldb + gn] : 0.f;
            }
        }
        __syncthreads();
#pragma unroll
        for (int kk = 0; kk < 32; kk++) {
            float a0 = As[kk][ty * 4 + 0];
            float a1 = As[kk][ty * 4 + 1];
            float a2 = As[kk][ty * 4 + 2];
            float a3 = As[kk][ty * 4 + 3];
            float b0 = Bs[kk][tx * 4 + 0];
            float b1 = Bs[kk][tx * 4 + 1];
            float b2 = Bs[kk][tx * 4 + 2];
            float b3 = Bs[kk][tx * 4 + 3];
            acc[0][0] = fmaf(a0, b0, acc[0][0]); acc[0][1] = fmaf(a0, b1, acc[0][1]);
            acc[0][2] = fmaf(a0, b2, acc[0][2]); acc[0][3] = fmaf(a0, b3, acc[0][3]);
            acc[1][0] = fmaf(a1, b0, acc[1][0]); acc[1][1] = fmaf(a1, b1, acc[1][1]);
            acc[1][2] = fmaf(a1, b2, acc[1][2]); acc[1][3] = fmaf(a1, b3, acc[1][3]);
            acc[2][0] = fmaf(a2, b0, acc[2][0]); acc[2][1] = fmaf(a2, b1, acc[2][1]);
            acc[2][2] = fmaf(a2, b2, acc[2][2]); acc[2][3] = fmaf(a2, b3, acc[2][3]);
            acc[3][0] = fmaf(a3, b0, acc[3][0]); acc[3][1] = fmaf(a3, b1, acc[3][1]);
            acc[3][2] = fmaf(a3, b2, acc[3][2]); acc[3][3] = fmaf(a3, b3, acc[3][3]);
        }
        __syncthreads();
    }
#pragma unroll
    for (int i = 0; i < 4; i++) {
        int gm = bm + ty * 4 + i;
        if (gm >= M) continue;
#pragma unroll
        for (int j = 0; j < 4; j++) {
            int gn = bn + tx * 4 + j;
            if (gn >= N) continue;
            float b = BIAS ? bias[gn] : 0.f;
            C[(size_t)gm * ldc + gn] = acc[i][j] + b;
        }
    }
}

// ---------------- K5: scores s[h][i] = w_h . x_i ----------------
// warp per node, many nodes per warp (weights live in registers, amortized)
__global__ void __launch_bounds__(256)
scores_kernel(const float* __restrict__ x, int n) {
    int warp_g = (blockIdx.x * 256 + threadIdx.x) >> 5;
    int lane = threadIdx.x & 31;
    int nwarps = gridDim.x * 8;

    float4 w[HNUM][3];
#pragma unroll
    for (int h = 0; h < HNUM; h++)
#pragma unroll
        for (int j = 0; j < 3; j++)
            w[h][j] = *(const float4*)(&g_wk[h * EDIM + j * 128 + lane * 4]);

    for (int i = warp_g; i < n; i += nwarps) {
        const float* row = x + (size_t)i * EDIM;
        float4 x0 = *(const float4*)(row + lane * 4);
        float4 x1 = *(const float4*)(row + 128 + lane * 4);
        float4 x2 = *(const float4*)(row + 256 + lane * 4);
        float p[HNUM];
#pragma unroll
        for (int h = 0; h < HNUM; h++) {
            float s;
            s = w[h][0].x * x0.x;                 s = fmaf(w[h][0].y, x0.y, s);
            s = fmaf(w[h][0].z, x0.z, s);         s = fmaf(w[h][0].w, x0.w, s);
            s = fmaf(w[h][1].x, x1.x, s);         s = fmaf(w[h][1].y, x1.y, s);
            s = fmaf(w[h][1].z, x1.z, s);         s = fmaf(w[h][1].w, x1.w, s);
            s = fmaf(w[h][2].x, x2.x, s);         s = fmaf(w[h][2].y, x2.y, s);
            s = fmaf(w[h][2].z, x2.z, s);         s = fmaf(w[h][2].w, x2.w, s);
            p[h] = s;
        }
#pragma unroll
        for (int sft = 16; sft > 0; sft >>= 1)
#pragma unroll
            for (int h = 0; h < HNUM; h++)
                p[h] += __shfl_xor_sync(0xffffffffu, p[h], sft);
        if (lane == 0) {
#pragma unroll
            for (int h = 0; h < HNUM; h++) g_scores[h * NMAX + i] = p[h];
        }
    }
}

// ---------------- K6: per-(group,head) softmax, in place ----------------
// G blocks x 192 threads; warp h handles head h. Register-resident (32 elems/lane).
__global__ void __launch_bounds__(192)
softmax_kernel(const int* __restrict__ sizes) {
    int g = blockIdx.x;
    int h = threadIdx.x >> 5;
    int lane = threadIdx.x & 31;
    int off = g_off[g];
    int size = sizes[g];
    float* sp = &g_scores[h * NMAX + off];

    float r[32];
#pragma unroll
    for (int j = 0; j < 32; j++) {
        int nn = lane + j * 32;
        r[j] = (nn < size) ? sp[nn] : -1e30f;
    }
    float m = -1e30f;
#pragma unroll
    for (int j = 0; j < 32; j++) m = fmaxf(m, r[j]);
    m = warp_max(m);
    float sum = 0.f;
#pragma unroll
    for (int j = 0; j < 32; j++) {
        int nn = lane + j * 32;
        float e = (nn < size) ? __expf(r[j] - m) : 0.f;
        r[j] = e;
        sum += e;
    }
    sum = warp_sum(sum);
    float inv = 1.f / sum;
#pragma unroll
    for (int j = 0; j < 32; j++) {
        int nn = lane + j * 32;
        if (nn < size) sp[nn] = r[j] * inv;
    }
}

// ---------------- K7: accumulate accx[g,h,e] += attn[h][i] * x[i][e] ----------------
// chunk of 128 nodes per block, thread per column e, atomic flush per group crossing.
__global__ void __launch_bounds__(384)
accum_kernel(const float* __restrict__ x, int n) {
    __shared__ float a_s[128][8];      // [node][head], padded to 8 for LDS.128
    __shared__ int off_s[GDIM + 1];
    int tid = threadIdx.x;
    int i0 = blockIdx.x * 128;
    int cnt = min(128, n - i0);

    for (int i = tid; i <= GDIM; i += 384) off_s[i] = g_off[i];
    for (int i = tid; i < HNUM * 128; i += 384) {
        int h = i >> 7, nn = i & 127;
        a_s[nn][h] = (nn < cnt) ? g_scores[h * NMAX + i0 + nn] : 0.f;
    }
    __syncthreads();

    // binary search: largest g with off[g] <= i0
    int lo = 0, hi = GDIM - 1;
    while (lo < hi) {
        int mid = (lo + hi + 1) >> 1;
        if (off_s[mid] <= i0) lo = mid; else hi = mid - 1;
    }
    int gid = lo;

    int e = tid;   // 0..383
    const float* px = x + (size_t)i0 * EDIM + e;
    float acc[HNUM];
#pragma unroll
    for (int h = 0; h < HNUM; h++) acc[h] = 0.f;

    for (int nn = 0; nn < cnt; nn++) {
        int i = i0 + nn;
        if (i >= off_s[gid + 1]) {
#pragma unroll
            for (int h = 0; h < HNUM; h++) {
                atomicAdd(&g_accx[(size_t)gid * HE + h * EDIM + e], acc[h]);
                acc[h] = 0.f;
            }
            gid++;
            while (i >= off_s[gid + 1]) gid++;
        }
        float xv = px[(size_t)nn * EDIM];
        float4 a4 = *(const float4*)&a_s[nn][0];
        float2 a2 = *(const float2*)&a_s[nn][4];
        acc[0] = fmaf(a4.x, xv, acc[0]);
        acc[1] = fmaf(a4.y, xv, acc[1]);
        acc[2] = fmaf(a4.z, xv, acc[2]);
        acc[3] = fmaf(a4.w, xv, acc[3]);
        acc[4] = fmaf(a2.x, xv, acc[4]);
        acc[5] = fmaf(a2.y, xv, acc[5]);
    }
#pragma unroll
    for (int h = 0; h < HNUM; h++)
        atomicAdd(&g_accx[(size_t)gid * HE + h * EDIM + e], acc[h]);
}

// ---------------- launch ----------------
extern "C" void kernel_launch(void* const* d_in, const int* in_sizes, int n_in,
                              void* d_out, int out_size) {
    const float* node_feat = (const float*)d_in[0];
    const int*   sizes     = (const int*)d_in[1];
    const float* query     = (const float*)d_in[2];
    const float* Wq        = (const float*)d_in[3];
    const float* bq        = (const float*)d_in[4];
    const float* Wk        = (const float*)d_in[5];
    /* bk = d_in[6] cancels in softmax */
    const float* Wv        = (const float*)d_in[7];
    const float* bv        = (const float*)d_in[8];
    const float* Wo        = (const float*)d_in[9];
    const float* bo        = (const float*)d_in[10];
    const float* Wp        = (const float*)d_in[11];
    const float* bp        = (const float*)d_in[12];
    float* out = (float*)d_out;

    int n = in_sizes[0] / EDIM;

    float *pWc, *pcb, *paccx, *ppooled;
    cudaGetSymbolAddress((void**)&pWc, g_Wc);
    cudaGetSymbolAddress((void**)&pcb, g_cb);
    cudaGetSymbolAddress((void**)&paccx, g_accx);
    cudaGetSymbolAddress((void**)&ppooled, g_pooled);

    cudaMemsetAsync(paccx, 0, (size_t)GDIM * HE * sizeof(float));

    // precompute
    qproj_kernel<<<96, 128>>>(Wq, query, bq);
    wkeff_kernel<<<HNUM, EDIM>>>(Wk);
    scan_kernel<<<1, GDIM>>>(sizes);
    cb_kernel<<<64, 128>>>(Wp, bo, bp);

    // Wc = Wp @ Wo   [256,384]
    gemm64<false, false><<<dim3(EDIM / 64, OUTD / 64, 1), 256>>>(
        Wp, EDIM, Wo, EDIM, pWc, EDIM, nullptr, OUTD, EDIM, EDIM, 0, 0, 0, 0);

    // attention pipeline
    scores_kernel<<<512, 256>>>(node_feat, n);
    softmax_kernel<<<GDIM, 192>>>(sizes);
    accum_kernel<<<(n + 127) / 128, 384>>>(node_feat, n);

    // pooled[g, h*64+jd] = bv + Wv_h . accx_h  — batched over h (grid.z)
    gemm64<true, true><<<dim3(1, GDIM / 64, HNUM), 256>>>(
        paccx, HE, Wv, EDIM, ppooled, EDIM, bv,
        GDIM, DHH, EDIM,
        /*zA=*/EDIM, /*zB=*/DHH * EDIM, /*zC=*/DHH, /*zBias=*/DHH);

    // out = pooled @ Wc^T + cb   [256,256]
    gemm64<true, true><<<dim3(OUTD / 64, GDIM / 64, 1), 256>>>(
        ppooled, EDIM, pWc, EDIM, out, OUTD, pcb,
        GDIM, OUTD, EDIM, 0, 0, 0, 0);
}

// round 5
// speedup vs baseline: 2.3111x; 1.3043x over previous
#include <cuda_runtime.h>
#include <math.h>

// Problem constants
#define EDIM 384
#define GDIM 256
#define HNUM 6
#define DHH  64
#define OUTD 256
#define NMAX 131072
#define HE   (HNUM*EDIM)   // 2304
#define CHUNK 64

// ---------------- device scratch ----------------
__device__ __align__(16) float g_q[EDIM];
__device__ __align__(16) float g_wk[HNUM*EDIM];
__device__ __align__(16) float g_Wc[OUTD*EDIM];      // Wp @ Wo
__device__ __align__(16) float g_cb[OUTD];           // Wp.bo + bp
__device__            int   g_off[GDIM + 1];
__device__ __align__(16) float g_accx[GDIM*HE];      // attn-weighted x sums
__device__ __align__(16) float g_pooled[GDIM*EDIM];  // pooled incl. bv

// ---------------- helpers ----------------
__device__ __forceinline__ float warp_sum(float v) {
#pragma unroll
    for (int s = 16; s > 0; s >>= 1) v += __shfl_xor_sync(0xffffffffu, v, s);
    return v;
}
__device__ __forceinline__ float warp_max(float v) {
#pragma unroll
    for (int s = 16; s > 0; s >>= 1) v = fmaxf(v, __shfl_xor_sync(0xffffffffu, v, s));
    return v;
}

// ---------------- prepA: qproj (blocks 0..47) + scan (48) + cb (49..80) ----
__global__ void __launch_bounds__(256)
prepA_kernel(const float* __restrict__ Wq, const float* __restrict__ query,
             const float* __restrict__ bq, const int* __restrict__ sizes,
             const float* __restrict__ Wp, const float* __restrict__ bo,
             const float* __restrict__ bp) {
    int b = blockIdx.x;
    int warp = threadIdx.x >> 5;
    int lane = threadIdx.x & 31;
    if (b < 48) {                       // q = (Wq @ query + bq)/8
        int gw = b * 8 + warp;
        float s = 0.f;
        for (int j = lane; j < EDIM; j += 32) s += Wq[(size_t)gw * EDIM + j] * query[j];
        s = warp_sum(s);
        if (lane == 0) g_q[gw] = (s + bq[gw]) * 0.125f;
    } else if (b == 48) {               // exclusive scan of sizes
        __shared__ int s[GDIM];
        int t = threadIdx.x;
        int v = sizes[t];
        s[t] = v;
        __syncthreads();
        for (int d = 1; d < GDIM; d <<= 1) {
            int add = (t >= d) ? s[t - d] : 0;
            __syncthreads();
            s[t] += add;
            __syncthreads();
        }
        g_off[t] = s[t] - v;
        if (t == GDIM - 1) g_off[GDIM] = s[t];
    } else {                            // cb[o] = Wp[o,:].bo + bp[o]
        int gw = (b - 49) * 8 + warp;
        float s = 0.f;
        for (int j = lane; j < EDIM; j += 32) s += Wp[(size_t)gw * EDIM + j] * bo[j];
        s = warp_sum(s);
        if (lane == 0) g_cb[gw] = s + bp[gw];
    }
}

// ---------------- prepB: w_h[e] = sum_d q[h*64+d] * Wk[h*64+d, e] ----------
__global__ void wkeff_kernel(const float* __restrict__ Wk) {
    int h = blockIdx.x;
    int e = threadIdx.x;
    __shared__ float qs[DHH];
    if (e < DHH) qs[e] = g_q[h * DHH + e];
    __syncthreads();
    float s = 0.f;
#pragma unroll 8
    for (int d = 0; d < DHH; d++)
        s += qs[d] * Wk[(size_t)(h * DHH + d) * EDIM + e];
    g_wk[h * EDIM + e] = s;
}

// ---------------- 64x32-tiled fp32 GEMM, 4x4 microtile, 128 threads ------
// C[M,N] = A[M,K] @ B (+ bias[n]).  B is [K,N] (TB=false) or [N,K] (TB=true).
// Batched over blockIdx.z via zA/zB/zC/zBias strides. M%64==0, N%32==0, K%32==0.
template <bool TB, bool BIAS>
__global__ void __launch_bounds__(128)
gemm_s(const float* __restrict__ A, int lda,
       const float* __restrict__ B, int ldb,
       float* __restrict__ C, int ldc,
       const float* __restrict__ bias,
       int M, int N, int K,
       int zA, int zB, int zC, int zBias) {
    A += (size_t)blockIdx.z * zA;
    B += (size_t)blockIdx.z * zB;
    C += (size_t)blockIdx.z * zC;
    if (BIAS) bias += (size_t)blockIdx.z * zBias;

    __shared__ float As[32][68];   // [k][m], stride mult of 4 for float4 LDS
    __shared__ float Bs[32][36];   // [k][n]
    int tid = threadIdx.x;
    int bm = blockIdx.y * 64, bn = blockIdx.x * 32;
    int tx = tid & 7, ty = tid >> 3;   // tx: 8 col-groups, ty: 16 row-groups

    float acc[4][4];
#pragma unroll
    for (int i = 0; i < 4; i++)
#pragma unroll
        for (int j = 0; j < 4; j++) acc[i][j] = 0.f;

    for (int k0 = 0; k0 < K; k0 += 32) {
        {   // A tile 64x32 -> As[k][m]; 16 elems/thread
            int kk = tid & 31, mb = tid >> 5;
#pragma unroll
            for (int i = 0; i < 16; i++) {
                int mm = mb + i * 4;
                As[kk][mm] = A[(size_t)(bm + mm) * lda + k0 + kk];
            }
        }
        if (TB) {   // B[N,K] -> Bs[k][n]; 8 elems/thread
            int kk = tid & 31, nb = tid >> 5;
#pragma unroll
            for (int i = 0; i < 8; i++) {
                int nn = nb + i * 4;
                Bs[kk][nn] = B[(size_t)(bn + nn) * ldb + k0 + kk];
            }
        } else {    // B[K,N] -> Bs[k][n]
            int nn = tid & 31, kb = tid >> 5;
#pragma unroll
            for (int i = 0; i < 8; i++) {
                int k2 = kb + i * 4;
                Bs[k2][nn] = B[(size_t)(k0 + k2) * ldb + bn + nn];
            }
        }
        __syncthreads();
#pragma unroll
        for (int kk = 0; kk < 32; kk++) {
            float4 a = *(const float4*)&As[kk][ty * 4];
            float4 bb = *(const float4*)&Bs[kk][tx * 4];
            acc[0][0] = fmaf(a.x, bb.x, acc[0][0]); acc[0][1] = fmaf(a.x, bb.y, acc[0][1]);
            acc[0][2] = fmaf(a.x, bb.z, acc[0][2]); acc[0][3] = fmaf(a.x, bb.w, acc[0][3]);
            acc[1][0] = fmaf(a.y, bb.x, acc[1][0]); acc[1][1] = fmaf(a.y, bb.y, acc[1][1]);
            acc[1][2] = fmaf(a.y, bb.z, acc[1][2]); acc[1][3] = fmaf(a.y, bb.w, acc[1][3]);
            acc[2][0] = fmaf(a.z, bb.x, acc[2][0]); acc[2][1] = fmaf(a.z, bb.y, acc[2][1]);
            acc[2][2] = fmaf(a.z, bb.z, acc[2][2]); acc[2][3] = fmaf(a.z, bb.w, acc[2][3]);
            acc[3][0] = fmaf(a.w, bb.x, acc[3][0]); acc[3][1] = fmaf(a.w, bb.y, acc[3][1]);
            acc[3][2] = fmaf(a.w, bb.z, acc[3][2]); acc[3][3] = fmaf(a.w, bb.w, acc[3][3]);
        }
        __syncthreads();
    }
    float4 bv4 = make_float4(0.f, 0.f, 0.f, 0.f);
    if (BIAS) bv4 = *(const float4*)&bias[bn + tx * 4];
#pragma unroll
    for (int i = 0; i < 4; i++) {
        int gm = bm + ty * 4 + i;
        float4 o = make_float4(acc[i][0] + bv4.x, acc[i][1] + bv4.y,
                               acc[i][2] + bv4.z, acc[i][3] + bv4.w);
        *(float4*)&C[(size_t)gm * ldc + bn + tx * 4] = o;
    }
}

// ---------------- fused attention: online softmax, single x read ----------
// one block per group, 384 threads (12 warps), chunks of 64 nodes.
__global__ void __launch_bounds__(384, 1)
attn_fused_kernel(const float* __restrict__ x, const int* __restrict__ sizes) {
    __shared__ float s_sc[CHUNK][8];         // [node][head] scores -> exp
    __shared__ float s_run_m[HNUM], s_run_sum[HNUM], s_scale[HNUM];

    int g = blockIdx.x;
    int off = g_off[g];
    int size = sizes[g];
    int tid = threadIdx.x;
    int warp = tid >> 5;
    int lane = tid & 31;

    if (tid < HNUM) { s_run_m[tid] = -1e30f; s_run_sum[tid] = 0.f; }

    // per-lane score weights in registers (72 regs)
    float4 w[HNUM][3];
#pragma unroll
    for (int h = 0; h < HNUM; h++)
#pragma unroll
        for (int j = 0; j < 3; j++)
            w[h][j] = *(const float4*)(&g_wk[h * EDIM + j * 128 + lane * 4]);

    float acc[HNUM];
#pragma unroll
    for (int h = 0; h < HNUM; h++) acc[h] = 0.f;

    const float* xe = x + (size_t)off * EDIM + tid;   // phase-3 column ptr
    __syncthreads();

    for (int c0 = 0; c0 < size; c0 += CHUNK) {
        int cnt = min(CHUNK, size - c0);

        // ---- phase 1: raw scores for chunk (warp per node) ----
        for (int nn = warp; nn < cnt; nn += 12) {
            const float* row = x + (size_t)(off + c0 + nn) * EDIM;
            float4 x0 = *(const float4*)(row + lane * 4);
            float4 x1 = *(const float4*)(row + 128 + lane * 4);
            float4 x2 = *(const float4*)(row + 256 + lane * 4);
            float p[HNUM];
#pragma unroll
            for (int h = 0; h < HNUM; h++) {
                float s;
                s = w[h][0].x * x0.x;           s = fmaf(w[h][0].y, x0.y, s);
                s = fmaf(w[h][0].z, x0.z, s);   s = fmaf(w[h][0].w, x0.w, s);
                s = fmaf(w[h][1].x, x1.x, s);   s = fmaf(w[h][1].y, x1.y, s);
                s = fmaf(w[h][1].z, x1.z, s);   s = fmaf(w[h][1].w, x1.w, s);
                s = fmaf(w[h][2].x, x2.x, s);   s = fmaf(w[h][2].y, x2.y, s);
                s = fmaf(w[h][2].z, x2.z, s);   s = fmaf(w[h][2].w, x2.w, s);
                p[h] = s;
            }
#pragma unroll
            for (int sft = 16; sft > 0; sft >>= 1)
#pragma unroll
                for (int h = 0; h < HNUM; h++)
                    p[h] += __shfl_xor_sync(0xffffffffu, p[h], sft);
            if (lane == 0) {
#pragma unroll
                for (int h = 0; h < HNUM; h++) s_sc[nn][h] = p[h];
            }
        }
        __syncthreads();

        // ---- phase 2: online softmax update (warp h owns head h) ----
        if (warp < HNUM) {
            int h = warp;
            float m = -1e30f;
            for (int nn = lane; nn < cnt; nn += 32) m = fmaxf(m, s_sc[nn][h]);
            m = warp_max(m);
            float newm = fmaxf(s_run_m[h], m);
            float sum = 0.f;
            for (int nn = lane; nn < cnt; nn += 32) {
                float e = __expf(s_sc[nn][h] - newm);
                s_sc[nn][h] = e;
                sum += e;
            }
            sum = warp_sum(sum);
            if (lane == 0) {
                float sc = __expf(s_run_m[h] - newm);
                s_scale[h] = sc;
                s_run_sum[h] = s_run_sum[h] * sc + sum;
                s_run_m[h] = newm;
            }
        }
        __syncthreads();

        // ---- phase 3: rescale + accumulate (thread per column) ----
#pragma unroll
        for (int h = 0; h < HNUM; h++) acc[h] *= s_scale[h];
        const float* px = xe + (size_t)c0 * EDIM;
        for (int nn = 0; nn < cnt; nn++) {
            float xv = px[(size_t)nn * EDIM];     // L1 hit (read in phase 1)
            float4 a4 = *(const float4*)&s_sc[nn][0];
            float2 a2 = *(const float2*)&s_sc[nn][4];
            acc[0] = fmaf(a4.x, xv, acc[0]);
            acc[1] = fmaf(a4.y, xv, acc[1]);
            acc[2] = fmaf(a4.z, xv, acc[2]);
            acc[3] = fmaf(a4.w, xv, acc[3]);
            acc[4] = fmaf(a2.x, xv, acc[4]);
            acc[5] = fmaf(a2.y, xv, acc[5]);
        }
        __syncthreads();
    }

#pragma unroll
    for (int h = 0; h < HNUM; h++)
        g_accx[(size_t)g * HE + h * EDIM + tid] = acc[h] * (1.f / s_run_sum[h]);
}

// ---------------- launch ----------------
extern "C" void kernel_launch(void* const* d_in, const int* in_sizes, int n_in,
                              void* d_out, int out_size) {
    const float* node_feat = (const float*)d_in[0];
    const int*   sizes     = (const int*)d_in[1];
    const float* query     = (const float*)d_in[2];
    const float* Wq        = (const float*)d_in[3];
    const float* bq        = (const float*)d_in[4];
    const float* Wk        = (const float*)d_in[5];
    /* bk = d_in[6] cancels in softmax */
    const float* Wv        = (const float*)d_in[7];
    const float* bv        = (const float*)d_in[8];
    const float* Wo        = (const float*)d_in[9];
    const float* bo        = (const float*)d_in[10];
    const float* Wp        = (const float*)d_in[11];
    const float* bp        = (const float*)d_in[12];
    float* out = (float*)d_out;

    float *pWc, *pcb, *paccx, *ppooled;
    cudaGetSymbolAddress((void**)&pWc, g_Wc);
    cudaGetSymbolAddress((void**)&pcb, g_cb);
    cudaGetSymbolAddress((void**)&paccx, g_accx);
    cudaGetSymbolAddress((void**)&ppooled, g_pooled);

    // prep: q-projection, scan, cb  (one launch) ; then effective K weights
    prepA_kernel<<<81, 256>>>(Wq, query, bq, sizes, Wp, bo, bp);
    wkeff_kernel<<<HNUM, EDIM>>>(Wk);

    // Wc = Wp @ Wo   [256,384] = [256,384]@[384,384]
    gemm_s<false, false><<<dim3(EDIM / 32, OUTD / 64, 1), 128>>>(
        Wp, EDIM, Wo, EDIM, pWc, EDIM, nullptr, OUTD, EDIM, EDIM, 0, 0, 0, 0);

    // fused attention -> accx[g, h*384+e]
    attn_fused_kernel<<<GDIM, 384>>>(node_feat, sizes);

    // pooled[g, h*64+d] = bv + Wv_h . accx_h   (batched over h)
    gemm_s<true, true><<<dim3(DHH / 32, GDIM / 64, HNUM), 128>>>(
        paccx, HE, Wv, EDIM, ppooled, EDIM, bv,
        GDIM, DHH, EDIM, /*zA=*/EDIM, /*zB=*/DHH * EDIM, /*zC=*/DHH, /*zBias=*/DHH);

    // out = pooled @ Wc^T + cb   [256,256]
    gemm_s<true, true><<<dim3(OUTD / 32, GDIM / 64, 1), 128>>>(
        ppooled, EDIM, pWc, EDIM, out, OUTD, pcb,
        GDIM, OUTD, EDIM, 0, 0, 0, 0);
}

// round 6
// speedup vs baseline: 2.5274x; 1.0936x over previous
#include <cuda_runtime.h>
#include <math.h>

// Problem constants
#define EDIM 384
#define GDIM 256
#define HNUM 6
#define DHH  64
#define OUTD 256
#define HE   (HNUM*EDIM)   // 2304
#define CHUNK 64
#define SMEM_X (CHUNK*EDIM*4)   // 98304 B

// ---------------- device scratch ----------------
__device__ __align__(16) float g_wk[HNUM*EDIM];
__device__ __align__(16) float g_Wc[OUTD*EDIM];      // Wp @ Wo
__device__ __align__(16) float g_cb[OUTD];           // Wp.bo + bp
__device__            int   g_off[GDIM + 1];
__device__ __align__(16) float g_accx[GDIM*HE];      // attn-weighted x sums
__device__ __align__(16) float g_pooled[GDIM*EDIM];  // pooled incl. bv

// ---------------- helpers ----------------
__device__ __forceinline__ float warp_sum(float v) {
#pragma unroll
    for (int s = 16; s > 0; s >>= 1) v += __shfl_xor_sync(0xffffffffu, v, s);
    return v;
}
__device__ __forceinline__ float warp_max(float v) {
#pragma unroll
    for (int s = 16; s > 0; s >>= 1) v = fmaxf(v, __shfl_xor_sync(0xffffffffu, v, s));
    return v;
}

// ---------------- wkq: q slice + effective score weights, per head ----------
// block h: q[h*64+d] = (Wq[h*64+d,:].query + bq)/8 ; w_h[e] = sum_d q_d * Wk[h*64+d, e]
__global__ void __launch_bounds__(EDIM)
wkq_kernel(const float* __restrict__ Wq, const float* __restrict__ query,
           const float* __restrict__ bq, const float* __restrict__ Wk) {
    int h = blockIdx.x;
    int tid = threadIdx.x;
    int warp = tid >> 5;
    int lane = tid & 31;
    __shared__ float qs[DHH];
    for (int d = warp; d < DHH; d += 12) {
        int row = h * DHH + d;
        float s = 0.f;
        for (int j = lane; j < EDIM; j += 32) s += Wq[(size_t)row * EDIM + j] * query[j];
        s = warp_sum(s);
        if (lane == 0) qs[d] = (s + bq[row]) * 0.125f;
    }
    __syncthreads();
    float s = 0.f;
#pragma unroll 8
    for (int d = 0; d < DHH; d++)
        s += qs[d] * Wk[(size_t)(h * DHH + d) * EDIM + tid];
    g_wk[h * EDIM + tid] = s;
}

// ---------------- prep: scan (block 0) + cb (blocks 1..32) -----------------
__global__ void __launch_bounds__(256)
prep_kernel(const int* __restrict__ sizes, const float* __restrict__ Wp,
            const float* __restrict__ bo, const float* __restrict__ bp) {
    int b = blockIdx.x;
    if (b == 0) {                       // exclusive scan of sizes
        __shared__ int s[GDIM];
        int t = threadIdx.x;
        int v = sizes[t];
        s[t] = v;
        __syncthreads();
        for (int d = 1; d < GDIM; d <<= 1) {
            int add = (t >= d) ? s[t - d] : 0;
            __syncthreads();
            s[t] += add;
            __syncthreads();
        }
        g_off[t] = s[t] - v;
        if (t == GDIM - 1) g_off[GDIM] = s[t];
    } else {                            // cb[o] = Wp[o,:].bo + bp[o]
        int warp = threadIdx.x >> 5;
        int lane = threadIdx.x & 31;
        int gw = (b - 1) * 8 + warp;
        float s = 0.f;
        for (int j = lane; j < EDIM; j += 32) s += Wp[(size_t)gw * EDIM + j] * bo[j];
        s = warp_sum(s);
        if (lane == 0) g_cb[gw] = s + bp[gw];
    }
}

// ---------------- 64x32-tiled fp32 GEMM, 4x4 microtile, 128 threads ------
template <bool TB, bool BIAS>
__global__ void __launch_bounds__(128)
gemm_s(const float* __restrict__ A, int lda,
       const float* __restrict__ B, int ldb,
       float* __restrict__ C, int ldc,
       const float* __restrict__ bias,
       int M, int N, int K,
       int zA, int zB, int zC, int zBias) {
    A += (size_t)blockIdx.z * zA;
    B += (size_t)blockIdx.z * zB;
    C += (size_t)blockIdx.z * zC;
    if (BIAS) bias += (size_t)blockIdx.z * zBias;

    __shared__ float As[32][68];
    __shared__ float Bs[32][36];
    int tid = threadIdx.x;
    int bm = blockIdx.y * 64, bn = blockIdx.x * 32;
    int tx = tid & 7, ty = tid >> 3;

    float acc[4][4];
#pragma unroll
    for (int i = 0; i < 4; i++)
#pragma unroll
        for (int j = 0; j < 4; j++) acc[i][j] = 0.f;

    for (int k0 = 0; k0 < K; k0 += 32) {
        {
            int kk = tid & 31, mb = tid >> 5;
#pragma unroll
            for (int i = 0; i < 16; i++) {
                int mm = mb + i * 4;
                As[kk][mm] = A[(size_t)(bm + mm) * lda + k0 + kk];
            }
        }
        if (TB) {
            int kk = tid & 31, nb = tid >> 5;
#pragma unroll
            for (int i = 0; i < 8; i++) {
                int nn = nb + i * 4;
                Bs[kk][nn] = B[(size_t)(bn + nn) * ldb + k0 + kk];
            }
        } else {
            int nn = tid & 31, kb = tid >> 5;
#pragma unroll
            for (int i = 0; i < 8; i++) {
                int k2 = kb + i * 4;
                Bs[k2][nn] = B[(size_t)(k0 + k2) * ldb + bn + nn];
            }
        }
        __syncthreads();
#pragma unroll
        for (int kk = 0; kk < 32; kk++) {
            float4 a = *(const float4*)&As[kk][ty * 4];
            float4 bb = *(const float4*)&Bs[kk][tx * 4];
            acc[0][0] = fmaf(a.x, bb.x, acc[0][0]); acc[0][1] = fmaf(a.x, bb.y, acc[0][1]);
            acc[0][2] = fmaf(a.x, bb.z, acc[0][2]); acc[0][3] = fmaf(a.x, bb.w, acc[0][3]);
            acc[1][0] = fmaf(a.y, bb.x, acc[1][0]); acc[1][1] = fmaf(a.y, bb.y, acc[1][1]);
            acc[1][2] = fmaf(a.y, bb.z, acc[1][2]); acc[1][3] = fmaf(a.y, bb.w, acc[1][3]);
            acc[2][0] = fmaf(a.z, bb.x, acc[2][0]); acc[2][1] = fmaf(a.z, bb.y, acc[2][1]);
            acc[2][2] = fmaf(a.z, bb.z, acc[2][2]); acc[2][3] = fmaf(a.z, bb.w, acc[2][3]);
            acc[3][0] = fmaf(a.w, bb.x, acc[3][0]); acc[3][1] = fmaf(a.w, bb.y, acc[3][1]);
            acc[3][2] = fmaf(a.w, bb.z, acc[3][2]); acc[3][3] = fmaf(a.w, bb.w, acc[3][3]);
        }
        __syncthreads();
    }
    float4 bv4 = make_float4(0.f, 0.f, 0.f, 0.f);
    if (BIAS) bv4 = *(const float4*)&bias[bn + tx * 4];
#pragma unroll
    for (int i = 0; i < 4; i++) {
        int gm = bm + ty * 4 + i;
        float4 o = make_float4(acc[i][0] + bv4.x, acc[i][1] + bv4.y,
                               acc[i][2] + bv4.z, acc[i][3] + bv4.w);
        *(float4*)&C[(size_t)gm * ldc + bn + tx * 4] = o;
    }
}

// ---------------- fused attention: smem-staged chunks, online softmax ------
// one block per group, 256 threads (8 warps), chunks of 64 nodes staged in smem.
extern __shared__ float x_s[];   // [CHUNK][EDIM]  (96 KB dynamic)

__global__ void __launch_bounds__(256, 2)
attn_fused_kernel(const float* __restrict__ x, const int* __restrict__ sizes) {
    __shared__ float s_sc[CHUNK][8];         // [node][head] scores -> exp
    __shared__ float s_run_m[HNUM], s_run_sum[HNUM], s_scale[HNUM];

    int g = blockIdx.x;
    int off = g_off[g];
    int size = sizes[g];
    int tid = threadIdx.x;
    int warp = tid >> 5;
    int lane = tid & 31;

    if (tid < HNUM) { s_run_m[tid] = -1e30f; s_run_sum[tid] = 0.f; }

    // per-lane score weights in registers (72 regs)
    float4 w[HNUM][3];
#pragma unroll
    for (int h = 0; h < HNUM; h++)
#pragma unroll
        for (int j = 0; j < 3; j++)
            w[h][j] = *(const float4*)(&g_wk[h * EDIM + j * 128 + lane * 4]);

    const bool two = (tid < 128);
    const int e2 = tid + 256;
    float acc1[HNUM], acc2[HNUM];
#pragma unroll
    for (int h = 0; h < HNUM; h++) { acc1[h] = 0.f; acc2[h] = 0.f; }

    float4* xs4 = (float4*)x_s;

    for (int c0 = 0; c0 < size; c0 += CHUNK) {
        int cnt = min(CHUNK, size - c0);

        // ---- phase 0: stage chunk in smem (coalesced burst) ----
        {
            const float4* gx = (const float4*)(x + (size_t)(off + c0) * EDIM);
            int nf4 = cnt * (EDIM / 4);
            for (int i = tid; i < nf4; i += 256) xs4[i] = gx[i];
        }
        __syncthreads();

        // ---- phase 1: raw scores (warp per node, x from smem) ----
        for (int nn = warp; nn < cnt; nn += 8) {
            const float4* rowv = (const float4*)(x_s + nn * EDIM);
            float4 x0 = rowv[lane];
            float4 x1 = rowv[lane + 32];
            float4 x2 = rowv[lane + 64];
            float p[HNUM];
#pragma unroll
            for (int h = 0; h < HNUM; h++) {
                float s;
                s = w[h][0].x * x0.x;           s = fmaf(w[h][0].y, x0.y, s);
                s = fmaf(w[h][0].z, x0.z, s);   s = fmaf(w[h][0].w, x0.w, s);
                s = fmaf(w[h][1].x, x1.x, s);   s = fmaf(w[h][1].y, x1.y, s);
                s = fmaf(w[h][1].z, x1.z, s);   s = fmaf(w[h][1].w, x1.w, s);
                s = fmaf(w[h][2].x, x2.x, s);   s = fmaf(w[h][2].y, x2.y, s);
                s = fmaf(w[h][2].z, x2.z, s);   s = fmaf(w[h][2].w, x2.w, s);
                p[h] = s;
            }
#pragma unroll
            for (int sft = 16; sft > 0; sft >>= 1)
#pragma unroll
                for (int h = 0; h < HNUM; h++)
                    p[h] += __shfl_xor_sync(0xffffffffu, p[h], sft);
            if (lane == 0) {
#pragma unroll
                for (int h = 0; h < HNUM; h++) s_sc[nn][h] = p[h];
            }
        }
        __syncthreads();

        // ---- phase 2: online softmax update (warp h owns head h) ----
        if (warp < HNUM) {
            int h = warp;
            float m = -1e30f;
            for (int nn = lane; nn < cnt; nn += 32) m = fmaxf(m, s_sc[nn][h]);
            m = warp_max(m);
            float newm = fmaxf(s_run_m[h], m);
            float sum = 0.f;
            for (int nn = lane; nn < cnt; nn += 32) {
                float e = __expf(s_sc[nn][h] - newm);
                s_sc[nn][h] = e;
                sum += e;
            }
            sum = warp_sum(sum);
            if (lane == 0) {
                float sc = __expf(s_run_m[h] - newm);
                s_scale[h] = sc;
                s_run_sum[h] = s_run_sum[h] * sc + sum;
                s_run_m[h] = newm;
            }
        }
        __syncthreads();

        // ---- phase 3: rescale + accumulate (1.5 cols/thread, x from smem) ----
#pragma unroll
        for (int h = 0; h < HNUM; h++) {
            float sc = s_scale[h];
            acc1[h] *= sc;
            acc2[h] *= sc;
        }
        for (int nn = 0; nn < cnt; nn++) {
            float xv1 = x_s[nn * EDIM + tid];
            float xv2 = two ? x_s[nn * EDIM + e2] : 0.f;
            float4 a4 = *(const float4*)&s_sc[nn][0];
            float2 a2 = *(const float2*)&s_sc[nn][4];
            acc1[0] = fmaf(a4.x, xv1, acc1[0]);  acc2[0] = fmaf(a4.x, xv2, acc2[0]);
            acc1[1] = fmaf(a4.y, xv1, acc1[1]);  acc2[1] = fmaf(a4.y, xv2, acc2[1]);
            acc1[2] = fmaf(a4.z, xv1, acc1[2]);  acc2[2] = fmaf(a4.z, xv2, acc2[2]);
            acc1[3] = fmaf(a4.w, xv1, acc1[3]);  acc2[3] = fmaf(a4.w, xv2, acc2[3]);
            acc1[4] = fmaf(a2.x, xv1, acc1[4]);  acc2[4] = fmaf(a2.x, xv2, acc2[4]);
            acc1[5] = fmaf(a2.y, xv1, acc1[5]);  acc2[5] = fmaf(a2.y, xv2, acc2[5]);
        }
        __syncthreads();
    }

#pragma unroll
    for (int h = 0; h < HNUM; h++) {
        float inv = 1.f / s_run_sum[h];
        g_accx[(size_t)g * HE + h * EDIM + tid] = acc1[h] * inv;
        if (two) g_accx[(size_t)g * HE + h * EDIM + e2] = acc2[h] * inv;
    }
}

// ---------------- launch ----------------
extern "C" void kernel_launch(void* const* d_in, const int* in_sizes, int n_in,
                              void* d_out, int out_size) {
    const float* node_feat = (const float*)d_in[0];
    const int*   sizes     = (const int*)d_in[1];
    const float* query     = (const float*)d_in[2];
    const float* Wq        = (const float*)d_in[3];
    const float* bq        = (const float*)d_in[4];
    const float* Wk        = (const float*)d_in[5];
    /* bk = d_in[6] cancels in softmax */
    const float* Wv        = (const float*)d_in[7];
    const float* bv        = (const float*)d_in[8];
    const float* Wo        = (const float*)d_in[9];
    const float* bo        = (const float*)d_in[10];
    const float* Wp        = (const float*)d_in[11];
    const float* bp        = (const float*)d_in[12];
    float* out = (float*)d_out;

    float *pWc, *pcb, *paccx, *ppooled;
    cudaGetSymbolAddress((void**)&pWc, g_Wc);
    cudaGetSymbolAddress((void**)&pcb, g_cb);
    cudaGetSymbolAddress((void**)&paccx, g_accx);
    cudaGetSymbolAddress((void**)&ppooled, g_pooled);

    cudaFuncSetAttribute(attn_fused_kernel,
                         cudaFuncAttributeMaxDynamicSharedMemorySize, SMEM_X);

    // prep
    wkq_kernel<<<HNUM, EDIM>>>(Wq, query, bq, Wk);
    prep_kernel<<<33, 256>>>(sizes, Wp, bo, bp);

    // Wc = Wp @ Wo   [256,384]
    gemm_s<false, false><<<dim3(EDIM / 32, OUTD / 64, 1), 128>>>(
        Wp, EDIM, Wo, EDIM, pWc, EDIM, nullptr, OUTD, EDIM, EDIM, 0, 0, 0, 0);

    // fused attention -> accx[g, h*384+e]
    attn_fused_kernel<<<GDIM, 256, SMEM_X>>>(node_feat, sizes);

    // pooled[g, h*64+d] = bv + Wv_h . accx_h   (batched over h)
    gemm_s<true, true><<<dim3(DHH / 32, GDIM / 64, HNUM), 128>>>(
        paccx, HE, Wv, EDIM, ppooled, EDIM, bv,
        GDIM, DHH, EDIM, /*zA=*/EDIM, /*zB=*/DHH * EDIM, /*zC=*/DHH, /*zBias=*/DHH);

    // out = pooled @ Wc^T + cb   [256,256]
    gemm_s<true, true><<<dim3(OUTD / 32, GDIM / 64, 1), 128>>>(
        ppooled, EDIM, pWc, EDIM, out, OUTD, pcb,
        GDIM, OUTD, EDIM, 0, 0, 0, 0);
}

// round 7
// speedup vs baseline: 3.1903x; 1.2623x over previous
#include <cuda_runtime.h>
#include <math.h>

// Problem constants
#define EDIM 384
#define GDIM 256
#define HNUM 6
#define DHH  64
#define OUTD 256
#define HE   (HNUM*EDIM)   // 2304
#define CHUNK 64
#define UNIT 128
#define SLOTS 8            // MAX_N 1024 / UNIT
#define SMEM_X (CHUNK*EDIM*4)   // 98304 B

// ---------------- device scratch ----------------
__device__ __align__(16) float g_wk[HNUM*EDIM];
__device__ __align__(16) float g_Wc[OUTD*EDIM];      // Wp @ Wo
__device__ __align__(16) float g_cb[OUTD];           // Wp.bo + bp
__device__            int   g_off[GDIM + 1];
__device__ __align__(16) float g_accx[GDIM*HE];      // merged attn-weighted x sums
__device__ __align__(16) float g_pooled[GDIM*EDIM];  // pooled incl. bv
// per-unit softmax partials
__device__ __align__(16) float g_pacc[GDIM*SLOTS*HE];      // ~19 MB
__device__ __align__(16) float g_pm[GDIM*SLOTS*HNUM];
__device__ __align__(16) float g_psum[GDIM*SLOTS*HNUM];

// ---------------- helpers ----------------
__device__ __forceinline__ float warp_sum(float v) {
#pragma unroll
    for (int s = 16; s > 0; s >>= 1) v += __shfl_xor_sync(0xffffffffu, v, s);
    return v;
}
__device__ __forceinline__ float warp_max(float v) {
#pragma unroll
    for (int s = 16; s > 0; s >>= 1) v = fmaxf(v, __shfl_xor_sync(0xffffffffu, v, s));
    return v;
}

// ---------------- prep: wkq (blocks 0..5) + scan (6) + cb (7..28) ----------
__global__ void __launch_bounds__(EDIM)
prep_kernel(const float* __restrict__ Wq, const float* __restrict__ query,
            const float* __restrict__ bq, const float* __restrict__ Wk,
            const int* __restrict__ sizes, const float* __restrict__ Wp,
            const float* __restrict__ bo, const float* __restrict__ bp) {
    int b = blockIdx.x;
    int tid = threadIdx.x;
    int warp = tid >> 5;
    int lane = tid & 31;
    if (b < HNUM) {
        // q slice + effective score weights for head b
        int h = b;
        __shared__ float qs[DHH];
        for (int d = warp; d < DHH; d += 12) {
            int row = h * DHH + d;
            float s = 0.f;
            for (int j = lane; j < EDIM; j += 32) s += Wq[(size_t)row * EDIM + j] * query[j];
            s = warp_sum(s);
            if (lane == 0) qs[d] = (s + bq[row]) * 0.125f;
        }
        __syncthreads();
        float s = 0.f;
#pragma unroll 8
        for (int d = 0; d < DHH; d++)
            s += qs[d] * Wk[(size_t)(h * DHH + d) * EDIM + tid];
        g_wk[h * EDIM + tid] = s;
    } else if (b == HNUM) {
        // exclusive scan of sizes (256 of 384 threads)
        __shared__ int s[GDIM];
        if (tid < GDIM) {
            int v = sizes[tid];
            s[tid] = v;
        }
        __syncthreads();
        for (int d = 1; d < GDIM; d <<= 1) {
            int add = (tid < GDIM && tid >= d) ? s[tid - d] : 0;
            __syncthreads();
            if (tid < GDIM) s[tid] += add;
            __syncthreads();
        }
        if (tid < GDIM) {
            g_off[tid] = s[tid] - sizes[tid];
            if (tid == GDIM - 1) g_off[GDIM] = s[tid];
        }
    } else {
        // cb[o] = Wp[o,:].bo + bp[o]
        int gw = (b - HNUM - 1) * 12 + warp;
        if (gw < OUTD) {
            float s = 0.f;
            for (int j = lane; j < EDIM; j += 32) s += Wp[(size_t)gw * EDIM + j] * bo[j];
            s = warp_sum(s);
            if (lane == 0) g_cb[gw] = s + bp[gw];
        }
    }
}

// ---------------- 64x32-tiled fp32 GEMM, 4x4 microtile, 128 threads ------
template <bool TB, bool BIAS>
__global__ void __launch_bounds__(128)
gemm_s(const float* __restrict__ A, int lda,
       const float* __restrict__ B, int ldb,
       float* __restrict__ C, int ldc,
       const float* __restrict__ bias,
       int M, int N, int K,
       int zA, int zB, int zC, int zBias) {
    A += (size_t)blockIdx.z * zA;
    B += (size_t)blockIdx.z * zB;
    C += (size_t)blockIdx.z * zC;
    if (BIAS) bias += (size_t)blockIdx.z * zBias;

    __shared__ float As[32][68];
    __shared__ float Bs[32][36];
    int tid = threadIdx.x;
    int bm = blockIdx.y * 64, bn = blockIdx.x * 32;
    int tx = tid & 7, ty = tid >> 3;

    float acc[4][4];
#pragma unroll
    for (int i = 0; i < 4; i++)
#pragma unroll
        for (int j = 0; j < 4; j++) acc[i][j] = 0.f;

    for (int k0 = 0; k0 < K; k0 += 32) {
        {
            int kk = tid & 31, mb = tid >> 5;
#pragma unroll
            for (int i = 0; i < 16; i++) {
                int mm = mb + i * 4;
                As[kk][mm] = A[(size_t)(bm + mm) * lda + k0 + kk];
            }
        }
        if (TB) {
            int kk = tid & 31, nb = tid >> 5;
#pragma unroll
            for (int i = 0; i < 8; i++) {
                int nn = nb + i * 4;
                Bs[kk][nn] = B[(size_t)(bn + nn) * ldb + k0 + kk];
            }
        } else {
            int nn = tid & 31, kb = tid >> 5;
#pragma unroll
            for (int i = 0; i < 8; i++) {
                int k2 = kb + i * 4;
                Bs[k2][nn] = B[(size_t)(k0 + k2) * ldb + bn + nn];
            }
        }
        __syncthreads();
#pragma unroll
        for (int kk = 0; kk < 32; kk++) {
            float4 a = *(const float4*)&As[kk][ty * 4];
            float4 bb = *(const float4*)&Bs[kk][tx * 4];
            acc[0][0] = fmaf(a.x, bb.x, acc[0][0]); acc[0][1] = fmaf(a.x, bb.y, acc[0][1]);
            acc[0][2] = fmaf(a.x, bb.z, acc[0][2]); acc[0][3] = fmaf(a.x, bb.w, acc[0][3]);
            acc[1][0] = fmaf(a.y, bb.x, acc[1][0]); acc[1][1] = fmaf(a.y, bb.y, acc[1][1]);
            acc[1][2] = fmaf(a.y, bb.z, acc[1][2]); acc[1][3] = fmaf(a.y, bb.w, acc[1][3]);
            acc[2][0] = fmaf(a.z, bb.x, acc[2][0]); acc[2][1] = fmaf(a.z, bb.y, acc[2][1]);
            acc[2][2] = fmaf(a.z, bb.z, acc[2][2]); acc[2][3] = fmaf(a.z, bb.w, acc[2][3]);
            acc[3][0] = fmaf(a.w, bb.x, acc[3][0]); acc[3][1] = fmaf(a.w, bb.y, acc[3][1]);
            acc[3][2] = fmaf(a.w, bb.z, acc[3][2]); acc[3][3] = fmaf(a.w, bb.w, acc[3][3]);
        }
        __syncthreads();
    }
    float4 bv4 = make_float4(0.f, 0.f, 0.f, 0.f);
    if (BIAS) bv4 = *(const float4*)&bias[bn + tx * 4];
#pragma unroll
    for (int i = 0; i < 4; i++) {
        int gm = bm + ty * 4 + i;
        float4 o = make_float4(acc[i][0] + bv4.x, acc[i][1] + bv4.y,
                               acc[i][2] + bv4.z, acc[i][3] + bv4.w);
        *(float4*)&C[(size_t)gm * ldc + bn + tx * 4] = o;
    }
}

// ---------------- attention unit kernel: partial softmax over <=128 nodes ----
// block = (group, slot): nodes [slot*128, min(slot*128+128, size)).
// 256 threads, chunks of 64 staged in 96 KB smem. Writes unnormalized partials.
extern __shared__ float x_s[];   // [CHUNK][EDIM]

__global__ void __launch_bounds__(256, 2)
attn_unit_kernel(const float* __restrict__ x, const int* __restrict__ sizes) {
    __shared__ float s_sc[CHUNK][8];
    __shared__ float s_run_m[HNUM], s_run_sum[HNUM], s_scale[HNUM];

    int u = blockIdx.x;
    int g = u >> 3;
    int slot = u & (SLOTS - 1);
    int size = sizes[g];
    int ustart = slot * UNIT;
    if (ustart >= size) return;
    int ucnt = min(UNIT, size - ustart);
    int off = g_off[g] + ustart;

    int tid = threadIdx.x;
    int warp = tid >> 5;
    int lane = tid & 31;

    if (tid < HNUM) { s_run_m[tid] = -1e30f; s_run_sum[tid] = 0.f; }

    // per-lane score weights (72 regs)
    float4 w[HNUM][3];
#pragma unroll
    for (int h = 0; h < HNUM; h++)
#pragma unroll
        for (int j = 0; j < 3; j++)
            w[h][j] = *(const float4*)(&g_wk[h * EDIM + j * 128 + lane * 4]);

    const bool two = (tid < 128);
    const int e2 = tid + 256;
    float acc1[HNUM], acc2[HNUM];
#pragma unroll
    for (int h = 0; h < HNUM; h++) { acc1[h] = 0.f; acc2[h] = 0.f; }

    float4* xs4 = (float4*)x_s;

    for (int c0 = 0; c0 < ucnt; c0 += CHUNK) {
        int cnt = min(CHUNK, ucnt - c0);

        // phase 0: stage chunk
        {
            const float4* gx = (const float4*)(x + (size_t)(off + c0) * EDIM);
            int nf4 = cnt * (EDIM / 4);
            for (int i = tid; i < nf4; i += 256) xs4[i] = gx[i];
        }
        __syncthreads();

        // phase 1: raw scores (warp per node)
        for (int nn = warp; nn < cnt; nn += 8) {
            const float4* rowv = (const float4*)(x_s + nn * EDIM);
            float4 x0 = rowv[lane];
            float4 x1 = rowv[lane + 32];
            float4 x2 = rowv[lane + 64];
            float p[HNUM];
#pragma unroll
            for (int h = 0; h < HNUM; h++) {
                float s;
                s = w[h][0].x * x0.x;           s = fmaf(w[h][0].y, x0.y, s);
                s = fmaf(w[h][0].z, x0.z, s);   s = fmaf(w[h][0].w, x0.w, s);
                s = fmaf(w[h][1].x, x1.x, s);   s = fmaf(w[h][1].y, x1.y, s);
                s = fmaf(w[h][1].z, x1.z, s);   s = fmaf(w[h][1].w, x1.w, s);
                s = fmaf(w[h][2].x, x2.x, s);   s = fmaf(w[h][2].y, x2.y, s);
                s = fmaf(w[h][2].z, x2.z, s);   s = fmaf(w[h][2].w, x2.w, s);
                p[h] = s;
            }
#pragma unroll
            for (int sft = 16; sft > 0; sft >>= 1)
#pragma unroll
                for (int h = 0; h < HNUM; h++)
                    p[h] += __shfl_xor_sync(0xffffffffu, p[h], sft);
            if (lane == 0) {
#pragma unroll
                for (int h = 0; h < HNUM; h++) s_sc[nn][h] = p[h];
            }
        }
        __syncthreads();

        // phase 2: online softmax update (warp h owns head h)
        if (warp < HNUM) {
            int h = warp;
            float m = -1e30f;
            for (int nn = lane; nn < cnt; nn += 32) m = fmaxf(m, s_sc[nn][h]);
            m = warp_max(m);
            float newm = fmaxf(s_run_m[h], m);
            float sum = 0.f;
            for (int nn = lane; nn < cnt; nn += 32) {
                float e = __expf(s_sc[nn][h] - newm);
                s_sc[nn][h] = e;
                sum += e;
            }
            sum = warp_sum(sum);
            if (lane == 0) {
                float sc = __expf(s_run_m[h] - newm);
                s_scale[h] = sc;
                s_run_sum[h] = s_run_sum[h] * sc + sum;
                s_run_m[h] = newm;
            }
        }
        __syncthreads();

        // phase 3: rescale + accumulate
#pragma unroll
        for (int h = 0; h < HNUM; h++) {
            float sc = s_scale[h];
            acc1[h] *= sc;
            acc2[h] *= sc;
        }
        for (int nn = 0; nn < cnt; nn++) {
            float xv1 = x_s[nn * EDIM + tid];
            float xv2 = two ? x_s[nn * EDIM + e2] : 0.f;
            float4 a4 = *(const float4*)&s_sc[nn][0];
            float2 a2 = *(const float2*)&s_sc[nn][4];
            acc1[0] = fmaf(a4.x, xv1, acc1[0]);  acc2[0] = fmaf(a4.x, xv2, acc2[0]);
            acc1[1] = fmaf(a4.y, xv1, acc1[1]);  acc2[1] = fmaf(a4.y, xv2, acc2[1]);
            acc1[2] = fmaf(a4.z, xv1, acc1[2]);  acc2[2] = fmaf(a4.z, xv2, acc2[2]);
            acc1[3] = fmaf(a4.w, xv1, acc1[3]);  acc2[3] = fmaf(a4.w, xv2, acc2[3]);
            acc1[4] = fmaf(a2.x, xv1, acc1[4]);  acc2[4] = fmaf(a2.x, xv2, acc2[4]);
            acc1[5] = fmaf(a2.y, xv1, acc1[5]);  acc2[5] = fmaf(a2.y, xv2, acc2[5]);
        }
        __syncthreads();
    }

    // write unnormalized partials
#pragma unroll
    for (int h = 0; h < HNUM; h++) {
        g_pacc[(size_t)u * HE + h * EDIM + tid] = acc1[h];
        if (two) g_pacc[(size_t)u * HE + h * EDIM + e2] = acc2[h];
    }
    if (tid < HNUM) {
        g_pm[u * HNUM + tid] = s_run_m[tid];
        g_psum[u * HNUM + tid] = s_run_sum[tid];
    }
}

// ---------------- merge partials -> normalized accx ----------------
__global__ void __launch_bounds__(EDIM)
merge_kernel(const int* __restrict__ sizes) {
    __shared__ float s_w[SLOTS][HNUM];     // per-slot weight = exp(m_s-M)/denom
    int g = blockIdx.x;
    int size = sizes[g];
    int nslots = (size + UNIT - 1) / UNIT;
    int tid = threadIdx.x;

    if (tid < HNUM) {
        int h = tid;
        float M = -1e30f;
        for (int s = 0; s < nslots; s++)
            M = fmaxf(M, g_pm[(g * SLOTS + s) * HNUM + h]);
        float denom = 0.f;
        for (int s = 0; s < nslots; s++) {
            float sc = __expf(g_pm[(g * SLOTS + s) * HNUM + h] - M);
            s_w[s][h] = sc;
            denom += sc * g_psum[(g * SLOTS + s) * HNUM + h];
        }
        float inv = 1.f / denom;
        for (int s = 0; s < nslots; s++) s_w[s][h] *= inv;
    }
    __syncthreads();

    float acc[HNUM];
#pragma unroll
    for (int h = 0; h < HNUM; h++) acc[h] = 0.f;
    for (int s = 0; s < nslots; s++) {
        const float* pp = &g_pacc[(size_t)(g * SLOTS + s) * HE + tid];
#pragma unroll
        for (int h = 0; h < HNUM; h++)
            acc[h] = fmaf(s_w[s][h], pp[h * EDIM], acc[h]);
    }
#pragma unroll
    for (int h = 0; h < HNUM; h++)
        g_accx[(size_t)g * HE + h * EDIM + tid] = acc[h];
}

// ---------------- launch ----------------
extern "C" void kernel_launch(void* const* d_in, const int* in_sizes, int n_in,
                              void* d_out, int out_size) {
    const float* node_feat = (const float*)d_in[0];
    const int*   sizes     = (const int*)d_in[1];
    const float* query     = (const float*)d_in[2];
    const float* Wq        = (const float*)d_in[3];
    const float* bq        = (const float*)d_in[4];
    const float* Wk        = (const float*)d_in[5];
    /* bk = d_in[6] cancels in softmax */
    const float* Wv        = (const float*)d_in[7];
    const float* bv        = (const float*)d_in[8];
    const float* Wo        = (const float*)d_in[9];
    const float* bo        = (const float*)d_in[10];
    const float* Wp        = (const float*)d_in[11];
    const float* bp        = (const float*)d_in[12];
    float* out = (float*)d_out;

    float *pWc, *pcb, *paccx, *ppooled;
    cudaGetSymbolAddress((void**)&pWc, g_Wc);
    cudaGetSymbolAddress((void**)&pcb, g_cb);
    cudaGetSymbolAddress((void**)&paccx, g_accx);
    cudaGetSymbolAddress((void**)&ppooled, g_pooled);

    cudaFuncSetAttribute(attn_unit_kernel,
                         cudaFuncAttributeMaxDynamicSharedMemorySize, SMEM_X);

    // prep: wkq + scan + cb in one launch
    prep_kernel<<<HNUM + 1 + 22, EDIM>>>(Wq, query, bq, Wk, sizes, Wp, bo, bp);

    // Wc = Wp @ Wo   [256,384]
    gemm_s<false, false><<<dim3(EDIM / 32, OUTD / 64, 1), 128>>>(
        Wp, EDIM, Wo, EDIM, pWc, EDIM, nullptr, OUTD, EDIM, EDIM, 0, 0, 0, 0);

    // attention partials + merge
    attn_unit_kernel<<<GDIM * SLOTS, 256, SMEM_X>>>(node_feat, sizes);
    merge_kernel<<<GDIM, EDIM>>>(sizes);

    // pooled[g, h*64+d] = bv + Wv_h . accx_h   (batched over h)
    gemm_s<true, true><<<dim3(DHH / 32, GDIM / 64, HNUM), 128>>>(
        paccx, HE, Wv, EDIM, ppooled, EDIM, bv,
        GDIM, DHH, EDIM, /*zA=*/EDIM, /*zB=*/DHH * EDIM, /*zC=*/DHH, /*zBias=*/DHH);

    // out = pooled @ Wc^T + cb   [256,256]
    gemm_s<true, true><<<dim3(OUTD / 32, GDIM / 64, 1), 128>>>(
        ppooled, EDIM, pWc, EDIM, out, OUTD, pcb,
        GDIM, OUTD, EDIM, 0, 0, 0, 0);
}

// round 8
// speedup vs baseline: 3.2277x; 1.0117x over previous
#include <cuda_runtime.h>
#include <math.h>
#include <stdint.h>

// Problem constants
#define EDIM 384
#define GDIM 256
#define HNUM 6
#define DHH  64
#define OUTD 256
#define HE   (HNUM*EDIM)   // 2304
#define CHUNK 32
#define UNIT 128
#define SLOTS 8            // MAX_N 1024 / UNIT
#define CFLOATS (CHUNK*EDIM)          // 12288 floats per buffer
#define SMEM_X (2*CFLOATS*4)          // 98304 B double buffer

// ---------------- device scratch ----------------
__device__ __align__(16) float g_wk[HNUM*EDIM];
__device__ __align__(16) float g_Wc[OUTD*EDIM];      // Wp @ Wo
__device__ __align__(16) float g_cb[OUTD];           // Wp.bo + bp
__device__            int   g_off[GDIM + 1];
__device__ __align__(16) float g_accx[GDIM*HE];      // merged attn-weighted x sums
__device__ __align__(16) float g_pooled[GDIM*EDIM];  // pooled incl. bv
// per-unit softmax partials; pacc layout [u][e][8] (heads padded to 8)
__device__ __align__(16) float g_pacc[(size_t)GDIM*SLOTS*EDIM*8];
__device__ __align__(16) float g_pm[GDIM*SLOTS*HNUM];
__device__ __align__(16) float g_psum[GDIM*SLOTS*HNUM];

// ---------------- helpers ----------------
__device__ __forceinline__ float warp_sum(float v) {
#pragma unroll
    for (int s = 16; s > 0; s >>= 1) v += __shfl_xor_sync(0xffffffffu, v, s);
    return v;
}
__device__ __forceinline__ float warp_max(float v) {
#pragma unroll
    for (int s = 16; s > 0; s >>= 1) v = fmaxf(v, __shfl_xor_sync(0xffffffffu, v, s));
    return v;
}
__device__ __forceinline__ void cp_async16(uint32_t saddr, const void* gaddr) {
    asm volatile("cp.async.cg.shared.global [%0], [%1], 16;" :: "r"(saddr), "l"(gaddr));
}
__device__ __forceinline__ void cp_commit() {
    asm volatile("cp.async.commit_group;");
}
__device__ __forceinline__ void cp_wait0() {
    asm volatile("cp.async.wait_group 0;");
}

// ---------------- prep: wkq (blocks 0..5) + scan (6) + cb (7..28) ----------
__global__ void __launch_bounds__(EDIM)
prep_kernel(const float* __restrict__ Wq, const float* __restrict__ query,
            const float* __restrict__ bq, const float* __restrict__ Wk,
            const int* __restrict__ sizes, const float* __restrict__ Wp,
            const float* __restrict__ bo, const float* __restrict__ bp) {
    int b = blockIdx.x;
    int tid = threadIdx.x;
    int warp = tid >> 5;
    int lane = tid & 31;
    if (b < HNUM) {
        int h = b;
        __shared__ float qs[DHH];
        for (int d = warp; d < DHH; d += 12) {
            int row = h * DHH + d;
            float s = 0.f;
            for (int j = lane; j < EDIM; j += 32) s += Wq[(size_t)row * EDIM + j] * query[j];
            s = warp_sum(s);
            if (lane == 0) qs[d] = (s + bq[row]) * 0.125f;
        }
        __syncthreads();
        float s = 0.f;
#pragma unroll 8
        for (int d = 0; d < DHH; d++)
            s += qs[d] * Wk[(size_t)(h * DHH + d) * EDIM + tid];
        g_wk[h * EDIM + tid] = s;
    } else if (b == HNUM) {
        __shared__ int s[GDIM];
        if (tid < GDIM) s[tid] = sizes[tid];
        __syncthreads();
        for (int d = 1; d < GDIM; d <<= 1) {
            int add = (tid < GDIM && tid >= d) ? s[tid - d] : 0;
            __syncthreads();
            if (tid < GDIM) s[tid] += add;
            __syncthreads();
        }
        if (tid < GDIM) {
            g_off[tid] = s[tid] - sizes[tid];
            if (tid == GDIM - 1) g_off[GDIM] = s[tid];
        }
    } else {
        int gw = (b - HNUM - 1) * 12 + warp;
        if (gw < OUTD) {
            float s = 0.f;
            for (int j = lane; j < EDIM; j += 32) s += Wp[(size_t)gw * EDIM + j] * bo[j];
            s = warp_sum(s);
            if (lane == 0) g_cb[gw] = s + bp[gw];
        }
    }
}

// ---------------- 64x32-tiled fp32 GEMM, 4x4 microtile, 128 threads ------
template <bool TB, bool BIAS>
__global__ void __launch_bounds__(128)
gemm_s(const float* __restrict__ A, int lda,
       const float* __restrict__ B, int ldb,
       float* __restrict__ C, int ldc,
       const float* __restrict__ bias,
       int M, int N, int K,
       int zA, int zB, int zC, int zBias) {
    A += (size_t)blockIdx.z * zA;
    B += (size_t)blockIdx.z * zB;
    C += (size_t)blockIdx.z * zC;
    if (BIAS) bias += (size_t)blockIdx.z * zBias;

    __shared__ float As[32][68];
    __shared__ float Bs[32][36];
    int tid = threadIdx.x;
    int bm = blockIdx.y * 64, bn = blockIdx.x * 32;
    int tx = tid & 7, ty = tid >> 3;

    float acc[4][4];
#pragma unroll
    for (int i = 0; i < 4; i++)
#pragma unroll
        for (int j = 0; j < 4; j++) acc[i][j] = 0.f;

    for (int k0 = 0; k0 < K; k0 += 32) {
        {
            int kk = tid & 31, mb = tid >> 5;
#pragma unroll
            for (int i = 0; i < 16; i++) {
                int mm = mb + i * 4;
                As[kk][mm] = A[(size_t)(bm + mm) * lda + k0 + kk];
            }
        }
        if (TB) {
            int kk = tid & 31, nb = tid >> 5;
#pragma unroll
            for (int i = 0; i < 8; i++) {
                int nn = nb + i * 4;
                Bs[kk][nn] = B[(size_t)(bn + nn) * ldb + k0 + kk];
            }
        } else {
            int nn = tid & 31, kb = tid >> 5;
#pragma unroll
            for (int i = 0; i < 8; i++) {
                int k2 = kb + i * 4;
                Bs[k2][nn] = B[(size_t)(k0 + k2) * ldb + bn + nn];
            }
        }
        __syncthreads();
#pragma unroll
        for (int kk = 0; kk < 32; kk++) {
            float4 a = *(const float4*)&As[kk][ty * 4];
            float4 bb = *(const float4*)&Bs[kk][tx * 4];
            acc[0][0] = fmaf(a.x, bb.x, acc[0][0]); acc[0][1] = fmaf(a.x, bb.y, acc[0][1]);
            acc[0][2] = fmaf(a.x, bb.z, acc[0][2]); acc[0][3] = fmaf(a.x, bb.w, acc[0][3]);
            acc[1][0] = fmaf(a.y, bb.x, acc[1][0]); acc[1][1] = fmaf(a.y, bb.y, acc[1][1]);
            acc[1][2] = fmaf(a.y, bb.z, acc[1][2]); acc[1][3] = fmaf(a.y, bb.w, acc[1][3]);
            acc[2][0] = fmaf(a.z, bb.x, acc[2][0]); acc[2][1] = fmaf(a.z, bb.y, acc[2][1]);
            acc[2][2] = fmaf(a.z, bb.z, acc[2][2]); acc[2][3] = fmaf(a.z, bb.w, acc[2][3]);
            acc[3][0] = fmaf(a.w, bb.x, acc[3][0]); acc[3][1] = fmaf(a.w, bb.y, acc[3][1]);
            acc[3][2] = fmaf(a.w, bb.z, acc[3][2]); acc[3][3] = fmaf(a.w, bb.w, acc[3][3]);
        }
        __syncthreads();
    }
    float4 bv4 = make_float4(0.f, 0.f, 0.f, 0.f);
    if (BIAS) bv4 = *(const float4*)&bias[bn + tx * 4];
#pragma unroll
    for (int i = 0; i < 4; i++) {
        int gm = bm + ty * 4 + i;
        float4 o = make_float4(acc[i][0] + bv4.x, acc[i][1] + bv4.y,
                               acc[i][2] + bv4.z, acc[i][3] + bv4.w);
        *(float4*)&C[(size_t)gm * ldc + bn + tx * 4] = o;
    }
}

// ---------------- attention unit kernel: cp.async double-buffered -----------
// block = (group, slot). 256 threads, chunks of 32 nodes, 2x48KB smem buffers.
extern __shared__ float x_s[];   // [2][CHUNK*EDIM]

__global__ void __launch_bounds__(256, 2)
attn_unit_kernel(const float* __restrict__ x, const int* __restrict__ sizes) {
    __shared__ float s_sc[CHUNK][8];
    __shared__ float s_run_m[HNUM], s_run_sum[HNUM], s_scale[HNUM];

    int u = blockIdx.x;
    int g = u >> 3;
    int slot = u & (SLOTS - 1);
    int size = sizes[g];
    int ustart = slot * UNIT;
    if (ustart >= size) return;
    int ucnt = min(UNIT, size - ustart);
    int off = g_off[g] + ustart;
    int nchunks = (ucnt + CHUNK - 1) / CHUNK;

    int tid = threadIdx.x;
    int warp = tid >> 5;
    int lane = tid & 31;

    if (tid < HNUM) { s_run_m[tid] = -1e30f; s_run_sum[tid] = 0.f; }

    uint32_t smem_base = (uint32_t)__cvta_generic_to_shared(x_s);

    // per-lane score weights (72 regs)
    float4 w[HNUM][3];
#pragma unroll
    for (int h = 0; h < HNUM; h++)
#pragma unroll
        for (int j = 0; j < 3; j++)
            w[h][j] = *(const float4*)(&g_wk[h * EDIM + j * 128 + lane * 4]);

    const bool two = (tid < 128);
    const int e2 = tid + 256;
    float acc1[HNUM], acc2[HNUM];
#pragma unroll
    for (int h = 0; h < HNUM; h++) { acc1[h] = 0.f; acc2[h] = 0.f; }

    // preload chunk 0 into buffer 0
    {
        int cnt0 = min(CHUNK, ucnt);
        const float4* gx = (const float4*)(x + (size_t)off * EDIM);
        int nf4 = cnt0 * (EDIM / 4);
        for (int i = tid; i < nf4; i += 256)
            cp_async16(smem_base + i * 16, gx + i);
    }
    cp_commit();

    for (int c = 0; c < nchunks; c++) {
        int c0 = c * CHUNK;
        int cnt = min(CHUNK, ucnt - c0);
        float* buf = x_s + (c & 1) * CFLOATS;

        cp_wait0();
        __syncthreads();

        // prefetch next chunk into the other buffer
        if (c + 1 < nchunks) {
            int n0 = (c + 1) * CHUNK;
            int cnt2 = min(CHUNK, ucnt - n0);
            const float4* gx = (const float4*)(x + (size_t)(off + n0) * EDIM);
            int nf4 = cnt2 * (EDIM / 4);
            uint32_t sb = smem_base + ((c + 1) & 1) * (CFLOATS * 4);
            for (int i = tid; i < nf4; i += 256)
                cp_async16(sb + i * 16, gx + i);
        }
        cp_commit();

        // phase 1: raw scores (warp per node)
        for (int nn = warp; nn < cnt; nn += 8) {
            const float4* rowv = (const float4*)(buf + nn * EDIM);
            float4 x0 = rowv[lane];
            float4 x1 = rowv[lane + 32];
            float4 x2 = rowv[lane + 64];
            float p[HNUM];
#pragma unroll
            for (int h = 0; h < HNUM; h++) {
                float s;
                s = w[h][0].x * x0.x;           s = fmaf(w[h][0].y, x0.y, s);
                s = fmaf(w[h][0].z, x0.z, s);   s = fmaf(w[h][0].w, x0.w, s);
                s = fmaf(w[h][1].x, x1.x, s);   s = fmaf(w[h][1].y, x1.y, s);
                s = fmaf(w[h][1].z, x1.z, s);   s = fmaf(w[h][1].w, x1.w, s);
                s = fmaf(w[h][2].x, x2.x, s);   s = fmaf(w[h][2].y, x2.y, s);
                s = fmaf(w[h][2].z, x2.z, s);   s = fmaf(w[h][2].w, x2.w, s);
                p[h] = s;
            }
#pragma unroll
            for (int sft = 16; sft > 0; sft >>= 1)
#pragma unroll
                for (int h = 0; h < HNUM; h++)
                    p[h] += __shfl_xor_sync(0xffffffffu, p[h], sft);
            if (lane == 0) {
#pragma unroll
                for (int h = 0; h < HNUM; h++) s_sc[nn][h] = p[h];
            }
        }
        __syncthreads();

        // phase 2: online softmax update (warp h owns head h)
        if (warp < HNUM) {
            int h = warp;
            float m = (lane < cnt) ? s_sc[lane][h] : -1e30f;
            m = warp_max(m);
            float newm = fmaxf(s_run_m[h], m);
            float e = (lane < cnt) ? __expf(s_sc[lane][h] - newm) : 0.f;
            if (lane < cnt) s_sc[lane][h] = e;
            float sum = warp_sum(e);
            if (lane == 0) {
                float sc = __expf(s_run_m[h] - newm);
                s_scale[h] = sc;
                s_run_sum[h] = s_run_sum[h] * sc + sum;
                s_run_m[h] = newm;
            }
        }
        __syncthreads();

        // phase 3: rescale + accumulate
#pragma unroll
        for (int h = 0; h < HNUM; h++) {
            float sc = s_scale[h];
            acc1[h] *= sc;
            acc2[h] *= sc;
        }
        for (int nn = 0; nn < cnt; nn++) {
            float xv1 = buf[nn * EDIM + tid];
            float xv2 = two ? buf[nn * EDIM + e2] : 0.f;
            float4 a4 = *(const float4*)&s_sc[nn][0];
            float2 a2 = *(const float2*)&s_sc[nn][4];
            acc1[0] = fmaf(a4.x, xv1, acc1[0]);  acc2[0] = fmaf(a4.x, xv2, acc2[0]);
            acc1[1] = fmaf(a4.y, xv1, acc1[1]);  acc2[1] = fmaf(a4.y, xv2, acc2[1]);
            acc1[2] = fmaf(a4.z, xv1, acc1[2]);  acc2[2] = fmaf(a4.z, xv2, acc2[2]);
            acc1[3] = fmaf(a4.w, xv1, acc1[3]);  acc2[3] = fmaf(a4.w, xv2, acc2[3]);
            acc1[4] = fmaf(a2.x, xv1, acc1[4]);  acc2[4] = fmaf(a2.x, xv2, acc2[4]);
            acc1[5] = fmaf(a2.y, xv1, acc1[5]);  acc2[5] = fmaf(a2.y, xv2, acc2[5]);
        }
        __syncthreads();
    }

    // write unnormalized partials: pacc[u][e][8], float4 pairs
    {
        float4* pp = (float4*)&g_pacc[((size_t)u * EDIM + tid) * 8];
        pp[0] = make_float4(acc1[0], acc1[1], acc1[2], acc1[3]);
        pp[1] = make_float4(acc1[4], acc1[5], 0.f, 0.f);
        if (two) {
            float4* pq = (float4*)&g_pacc[((size_t)u * EDIM + e2) * 8];
            pq[0] = make_float4(acc2[0], acc2[1], acc2[2], acc2[3]);
            pq[1] = make_float4(acc2[4], acc2[5], 0.f, 0.f);
        }
    }
    if (tid < HNUM) {
        g_pm[u * HNUM + tid] = s_run_m[tid];
        g_psum[u * HNUM + tid] = s_run_sum[tid];
    }
}

// ---------------- merge partials -> normalized accx ----------------
__global__ void __launch_bounds__(EDIM)
merge_kernel(const int* __restrict__ sizes) {
    __shared__ float s_w[SLOTS][HNUM];
    int g = blockIdx.x;
    int size = sizes[g];
    int nslots = (size + UNIT - 1) / UNIT;
    int tid = threadIdx.x;

    if (tid < HNUM) {
        int h = tid;
        float M = -1e30f;
        for (int s = 0; s < nslots; s++)
            M = fmaxf(M, g_pm[(g * SLOTS + s) * HNUM + h]);
        float denom = 0.f;
        for (int s = 0; s < nslots; s++) {
            float sc = __expf(g_pm[(g * SLOTS + s) * HNUM + h] - M);
            s_w[s][h] = sc;
            denom += sc * g_psum[(g * SLOTS + s) * HNUM + h];
        }
        float inv = 1.f / denom;
        for (int s = 0; s < nslots; s++) s_w[s][h] *= inv;
    }
    __syncthreads();

    float acc[HNUM];
#pragma unroll
    for (int h = 0; h < HNUM; h++) acc[h] = 0.f;
    for (int s = 0; s < nslots; s++) {
        const float4* pp = (const float4*)&g_pacc[((size_t)(g * SLOTS + s) * EDIM + tid) * 8];
        float4 p0 = pp[0];
        float4 p1 = pp[1];
        acc[0] = fmaf(s_w[s][0], p0.x, acc[0]);
        acc[1] = fmaf(s_w[s][1], p0.y, acc[1]);
        acc[2] = fmaf(s_w[s][2], p0.z, acc[2]);
        acc[3] = fmaf(s_w[s][3], p0.w, acc[3]);
        acc[4] = fmaf(s_w[s][4], p1.x, acc[4]);
        acc[5] = fmaf(s_w[s][5], p1.y, acc[5]);
    }
#pragma unroll
    for (int h = 0; h < HNUM; h++)
        g_accx[(size_t)g * HE + h * EDIM + tid] = acc[h];
}

// ---------------- launch ----------------
extern "C" void kernel_launch(void* const* d_in, const int* in_sizes, int n_in,
                              void* d_out, int out_size) {
    const float* node_feat = (const float*)d_in[0];
    const int*   sizes     = (const int*)d_in[1];
    const float* query     = (const float*)d_in[2];
    const float* Wq        = (const float*)d_in[3];
    const float* bq        = (const float*)d_in[4];
    const float* Wk        = (const float*)d_in[5];
    /* bk = d_in[6] cancels in softmax */
    const float* Wv        = (const float*)d_in[7];
    const float* bv        = (const float*)d_in[8];
    const float* Wo        = (const float*)d_in[9];
    const float* bo        = (const float*)d_in[10];
    const float* Wp        = (const float*)d_in[11];
    const float* bp        = (const float*)d_in[12];
    float* out = (float*)d_out;

    float *pWc, *pcb, *paccx, *ppooled;
    cudaGetSymbolAddress((void**)&pWc, g_Wc);
    cudaGetSymbolAddress((void**)&pcb, g_cb);
    cudaGetSymbolAddress((void**)&paccx, g_accx);
    cudaGetSymbolAddress((void**)&ppooled, g_pooled);

    cudaFuncSetAttribute(attn_unit_kernel,
                         cudaFuncAttributeMaxDynamicSharedMemorySize, SMEM_X);

    // prep: wkq + scan + cb in one launch
    prep_kernel<<<HNUM + 1 + 22, EDIM>>>(Wq, query, bq, Wk, sizes, Wp, bo, bp);

    // Wc = Wp @ Wo   [256,384]
    gemm_s<false, false><<<dim3(EDIM / 32, OUTD / 64, 1), 128>>>(
        Wp, EDIM, Wo, EDIM, pWc, EDIM, nullptr, OUTD, EDIM, EDIM, 0, 0, 0, 0);

    // attention partials + merge
    attn_unit_kernel<<<GDIM * SLOTS, 256, SMEM_X>>>(node_feat, sizes);
    merge_kernel<<<GDIM, EDIM>>>(sizes);

    // pooled[g, h*64+d] = bv + Wv_h . accx_h   (batched over h)
    gemm_s<true, true><<<dim3(DHH / 32, GDIM / 64, HNUM), 128>>>(
        paccx, HE, Wv, EDIM, ppooled, EDIM, bv,
        GDIM, DHH, EDIM, /*zA=*/EDIM, /*zB=*/DHH * EDIM, /*zC=*/DHH, /*zBias=*/DHH);

    // out = pooled @ Wc^T + cb   [256,256]
    gemm_s<true, true><<<dim3(OUTD / 32, GDIM / 64, 1), 128>>>(
        ppooled, EDIM, pWc, EDIM, out, OUTD, pcb,
        GDIM, OUTD, EDIM, 0, 0, 0, 0);
}